// round 1
// baseline (speedup 1.0000x reference)
#include <cuda_runtime.h>

#define BB   32
#define CINC 32
#define COUTC 32
#define TT   2048
#define DKK  32
#define LL   128
#define NBLK 16   // TT / LL

// Scratch (device globals: allocation-free per harness rules)
__device__ float g_buf[COUTC * CINC * TT];   // [o*32+i][d], d in [0,2048)
__device__ float xT_buf[CINC * TT * BB];     // [i][s][b]

// ---------------------------------------------------------------------------
// Stage 1a: transpose x[b][i][s] -> xT[i][s][b]
// grid (64, 32) = (s-block, i), threads (32, 8)
// ---------------------------------------------------------------------------
__global__ void transpose_kernel(const float* __restrict__ x) {
    __shared__ float tile[32][33];
    const int sb = blockIdx.x;
    const int i  = blockIdx.y;
    const int tx = threadIdx.x, ty = threadIdx.y;
    const int s0 = sb * 32;
#pragma unroll
    for (int k = 0; k < 4; k++) {
        int b = ty + k * 8;
        tile[b][tx] = x[(b * CINC + i) * TT + s0 + tx];   // coalesced in tx
    }
    __syncthreads();
#pragma unroll
    for (int k = 0; k < 4; k++) {
        int ss = ty + k * 8;
        xT_buf[(i * TT + s0 + ss) * BB + tx] = tile[tx][ss];  // coalesced in tx
    }
}

// ---------------------------------------------------------------------------
// Stage 1b: SIREN MLP -> g_buf.
// kern[o,i,k] = w3 @ sin(o2*(w2 @ sin(o1*(w1*pos_k + b1)) + b2)) + b3
// g[o,i,d] = kern[o,i,2048-d], d in [0,2048). (kern[...,0] is unused.)
// grid (16, 8) = (k-chunk of 128, j2-chunk of 128), 256 threads
// ---------------------------------------------------------------------------
__global__ void gen_kernel(const float* __restrict__ rel_pos,
                           const float* __restrict__ w1,
                           const float* __restrict__ b1,
                           const float* __restrict__ omega1p,
                           const float* __restrict__ w2,
                           const float* __restrict__ b2,
                           const float* __restrict__ omega2p,
                           const float* __restrict__ w3,
                           const float* __restrict__ b3) {
    __shared__ float h2s[128][33];
    const int tid = threadIdx.x;

    if (tid < 128) {
        const int kl = tid;
        const int k  = 1 + blockIdx.x * 128 + kl;   // k in [1, 2048]
        const float pos = rel_pos[k];
        const float o1 = *omega1p, o2 = *omega2p;
        float h1[DKK];
#pragma unroll
        for (int j = 0; j < DKK; j++)
            h1[j] = sinf(o1 * (w1[j] * pos + b1[j]));
        for (int j = 0; j < DKK; j++) {
            float a = b2[j];
#pragma unroll
            for (int l = 0; l < DKK; l++)
                a += w2[j * DKK + l] * h1[l];
            h2s[kl][j] = sinf(o2 * a);
        }
    }
    __syncthreads();

    const int kl   = tid & 127;
    const int half = tid >> 7;
    const int k    = 1 + blockIdx.x * 128 + kl;
    const int d    = 2048 - k;                       // d in [0, 2047]
    const int j2b  = blockIdx.y * 128 + half * 64;
    for (int jj = 0; jj < 64; jj++) {
        const int j2 = j2b + jj;
        float a = b3[j2];
#pragma unroll
        for (int l = 0; l < DKK; l++)
            a += w3[j2 * DKK + l] * h2s[kl][l];      // warp-broadcast LDG + LDS
        g_buf[j2 * TT + d] = a;                      // coalesced (lanes vary d)
    }
}

// ---------------------------------------------------------------------------
// Stage 2: blocked Toeplitz conv.
// Block (p-block of 128 t's, o). C tile = [tt=128 x b=32] fp32 accumulators.
// For q=0..p, i=0..31: smem <- x tile xT[i][qL..qL+127][0..31] (16 KB)
//                      smem <- g band g[o,i, rL-127 .. rL+127] (255 taps, 0 if d<0)
// Thread = (trow 0..15 -> 8 tt's, bq 0..15 -> 2 b's), 11-reg sliding g window.
// ---------------------------------------------------------------------------
__global__ void __launch_bounds__(256)
conv_kernel(const float* __restrict__ bias, float* __restrict__ out) {
    __shared__ float gs[256];
    __shared__ float xs[LL * BB];   // [ss][b]

    const int p  = (NBLK - 1) - blockIdx.x;   // heavy blocks first
    const int o  = blockIdx.y;
    const int tid  = threadIdx.x;
    const int bq   = tid & 15;
    const int trow = tid >> 4;
    const int tt0  = trow * 8;
    const int b0   = bq * 2;

    const float bv = bias[o];
    float acc[8][2];
#pragma unroll
    for (int j = 0; j < 8; j++) { acc[j][0] = bv; acc[j][1] = bv; }

    for (int q = 0; q <= p; ++q) {
        const int r = p - q;
        const float* gsrc = &g_buf[(o * CINC) * TT];  // + i*TT below
        for (int i = 0; i < CINC; ++i) {
            __syncthreads();   // previous compute done before overwrite
            // x tile: 4096 contiguous floats
            const float4* xsrc = (const float4*)&xT_buf[(i * TT + q * LL) * BB];
            float4* xd = (float4*)xs;
#pragma unroll
            for (int u = 0; u < 4; u++)
                xd[tid + u * 256] = xsrc[tid + u * 256];
            // g band (zero-fill for d<0 handles causality at r==0)
            if (tid < 255) {
                const int d = r * LL - 127 + tid;
                gs[tid] = (d >= 0) ? gsrc[i * TT + d] : 0.0f;
            }
            __syncthreads();

            for (int ss = 0; ss < LL; ss += 4) {
                float gw[11];
#pragma unroll
                for (int w = 0; w < 11; w++)
                    gw[w] = gs[tt0 + 124 - ss + w];
#pragma unroll
                for (int u = 0; u < 4; u++) {
                    const float2 xv = *(const float2*)&xs[(ss + u) * BB + b0];
#pragma unroll
                    for (int j = 0; j < 8; j++) {
                        const float gv = gw[j - u + 3];
                        acc[j][0] += gv * xv.x;
                        acc[j][1] += gv * xv.y;
                    }
                }
            }
        }
    }

    // write: 4x STG.128 per thread (t-contiguous groups of 4)
    const int tbase = p * LL + tt0;
#pragma unroll
    for (int bb = 0; bb < 2; bb++) {
        float* obase = &out[((b0 + bb) * COUTC + o) * TT + tbase];
        float4 v0 = make_float4(acc[0][bb], acc[1][bb], acc[2][bb], acc[3][bb]);
        float4 v1 = make_float4(acc[4][bb], acc[5][bb], acc[6][bb], acc[7][bb]);
        *(float4*)(obase)     = v0;
        *(float4*)(obase + 4) = v1;
    }
}

// ---------------------------------------------------------------------------
extern "C" void kernel_launch(void* const* d_in, const int* in_sizes, int n_in,
                              void* d_out, int out_size) {
    const float* x       = (const float*)d_in[0];
    const float* rel_pos = (const float*)d_in[1];
    const float* w1      = (const float*)d_in[2];
    const float* b1      = (const float*)d_in[3];
    const float* omega1  = (const float*)d_in[4];
    const float* w2      = (const float*)d_in[5];
    const float* b2      = (const float*)d_in[6];
    const float* omega2  = (const float*)d_in[7];
    const float* w3      = (const float*)d_in[8];
    const float* b3      = (const float*)d_in[9];
    const float* bias    = (const float*)d_in[10];
    float* out = (float*)d_out;

    transpose_kernel<<<dim3(64, 32), dim3(32, 8)>>>(x);
    gen_kernel<<<dim3(16, 8), 256>>>(rel_pos, w1, b1, omega1, w2, b2, omega2, w3, b3);
    conv_kernel<<<dim3(16, 32), 256>>>(bias, out);
}

// round 2
// speedup vs baseline: 1.0013x; 1.0013x over previous
#include <cuda_runtime.h>

#define BB   32
#define CINC 32
#define COUTC 32
#define TT   2048
#define DKK  32
#define LL   128
#define NBLK 16   // TT / LL

// Scratch (device globals: allocation-free per harness rules)
__device__ float g_buf[COUTC * CINC * TT];   // [o*32+i][d], d in [0,2048)
__device__ float xT_buf[CINC * TT * BB];     // [i][s][b]

// ---------------------------------------------------------------------------
// Stage 1a: transpose x[b][i][s] -> xT[i][s][b]
// grid (64, 32) = (s-block, i), threads (32, 8)
// ---------------------------------------------------------------------------
__global__ void transpose_kernel(const float* __restrict__ x) {
    __shared__ float tile[32][33];
    const int sb = blockIdx.x;
    const int i  = blockIdx.y;
    const int tx = threadIdx.x, ty = threadIdx.y;
    const int s0 = sb * 32;
#pragma unroll
    for (int k = 0; k < 4; k++) {
        int b = ty + k * 8;
        tile[b][tx] = x[(b * CINC + i) * TT + s0 + tx];   // coalesced in tx
    }
    __syncthreads();
#pragma unroll
    for (int k = 0; k < 4; k++) {
        int ss = ty + k * 8;
        xT_buf[(i * TT + s0 + ss) * BB + tx] = tile[tx][ss];  // coalesced in tx
    }
}

// ---------------------------------------------------------------------------
// Stage 1b: SIREN MLP -> g_buf.
// kern[o,i,k] = w3 @ sin(o2*(w2 @ sin(o1*(w1*pos_k + b1)) + b2)) + b3
// g[o,i,d] = kern[o,i,2048-d], d in [0,2048). (kern[...,0] is unused.)
// grid (16, 8) = (k-chunk of 128, j2-chunk of 128), 256 threads
// ---------------------------------------------------------------------------
__global__ void gen_kernel(const float* __restrict__ rel_pos,
                           const float* __restrict__ w1,
                           const float* __restrict__ b1,
                           const float* __restrict__ omega1p,
                           const float* __restrict__ w2,
                           const float* __restrict__ b2,
                           const float* __restrict__ omega2p,
                           const float* __restrict__ w3,
                           const float* __restrict__ b3) {
    __shared__ float h2s[128][33];
    const int tid = threadIdx.x;

    if (tid < 128) {
        const int kl = tid;
        const int k  = 1 + blockIdx.x * 128 + kl;   // k in [1, 2048]
        const float pos = rel_pos[k];
        const float o1 = *omega1p, o2 = *omega2p;
        float h1[DKK];
#pragma unroll
        for (int j = 0; j < DKK; j++)
            h1[j] = sinf(o1 * (w1[j] * pos + b1[j]));
        for (int j = 0; j < DKK; j++) {
            float a = b2[j];
#pragma unroll
            for (int l = 0; l < DKK; l++)
                a += w2[j * DKK + l] * h1[l];
            h2s[kl][j] = sinf(o2 * a);
        }
    }
    __syncthreads();

    const int kl   = tid & 127;
    const int half = tid >> 7;
    const int k    = 1 + blockIdx.x * 128 + kl;
    const int d    = 2048 - k;                       // d in [0, 2047]
    const int j2b  = blockIdx.y * 128 + half * 64;
    for (int jj = 0; jj < 64; jj++) {
        const int j2 = j2b + jj;
        float a = b3[j2];
#pragma unroll
        for (int l = 0; l < DKK; l++)
            a += w3[j2 * DKK + l] * h2s[kl][l];      // warp-broadcast LDG + LDS
        g_buf[j2 * TT + d] = a;                      // coalesced (lanes vary d)
    }
}

// ---------------------------------------------------------------------------
// Stage 2: blocked Toeplitz conv.
// Block (p-block of 128 t's, o). C tile = [tt=128 x b=32] fp32 accumulators.
// For q=0..p, i=0..31: smem <- x tile xT[i][qL..qL+127][0..31] (16 KB)
//                      smem <- g band g[o,i, rL-127 .. rL+127] (255 taps, 0 if d<0)
// Thread = (trow 0..15 -> 8 tt's, bq 0..15 -> 2 b's), 11-reg sliding g window.
// ---------------------------------------------------------------------------
__global__ void __launch_bounds__(256)
conv_kernel(const float* __restrict__ bias, float* __restrict__ out) {
    __shared__ float gs[256];
    __shared__ float xs[LL * BB];   // [ss][b]

    const int p  = (NBLK - 1) - blockIdx.x;   // heavy blocks first
    const int o  = blockIdx.y;
    const int tid  = threadIdx.x;
    const int bq   = tid & 15;
    const int trow = tid >> 4;
    const int tt0  = trow * 8;
    const int b0   = bq * 2;

    const float bv = bias[o];
    float acc[8][2];
#pragma unroll
    for (int j = 0; j < 8; j++) { acc[j][0] = bv; acc[j][1] = bv; }

    for (int q = 0; q <= p; ++q) {
        const int r = p - q;
        const float* gsrc = &g_buf[(o * CINC) * TT];  // + i*TT below
        for (int i = 0; i < CINC; ++i) {
            __syncthreads();   // previous compute done before overwrite
            // x tile: 4096 contiguous floats
            const float4* xsrc = (const float4*)&xT_buf[(i * TT + q * LL) * BB];
            float4* xd = (float4*)xs;
#pragma unroll
            for (int u = 0; u < 4; u++)
                xd[tid + u * 256] = xsrc[tid + u * 256];
            // g band (zero-fill for d<0 handles causality at r==0)
            if (tid < 255) {
                const int d = r * LL - 127 + tid;
                gs[tid] = (d >= 0) ? gsrc[i * TT + d] : 0.0f;
            }
            __syncthreads();

            for (int ss = 0; ss < LL; ss += 4) {
                float gw[11];
#pragma unroll
                for (int w = 0; w < 11; w++)
                    gw[w] = gs[tt0 + 124 - ss + w];
#pragma unroll
                for (int u = 0; u < 4; u++) {
                    const float2 xv = *(const float2*)&xs[(ss + u) * BB + b0];
#pragma unroll
                    for (int j = 0; j < 8; j++) {
                        const float gv = gw[j - u + 3];
                        acc[j][0] += gv * xv.x;
                        acc[j][1] += gv * xv.y;
                    }
                }
            }
        }
    }

    // write: 4x STG.128 per thread (t-contiguous groups of 4)
    const int tbase = p * LL + tt0;
#pragma unroll
    for (int bb = 0; bb < 2; bb++) {
        float* obase = &out[((b0 + bb) * COUTC + o) * TT + tbase];
        float4 v0 = make_float4(acc[0][bb], acc[1][bb], acc[2][bb], acc[3][bb]);
        float4 v1 = make_float4(acc[4][bb], acc[5][bb], acc[6][bb], acc[7][bb]);
        *(float4*)(obase)     = v0;
        *(float4*)(obase + 4) = v1;
    }
}

// ---------------------------------------------------------------------------
extern "C" void kernel_launch(void* const* d_in, const int* in_sizes, int n_in,
                              void* d_out, int out_size) {
    const float* x       = (const float*)d_in[0];
    const float* rel_pos = (const float*)d_in[1];
    const float* w1      = (const float*)d_in[2];
    const float* b1      = (const float*)d_in[3];
    const float* omega1  = (const float*)d_in[4];
    const float* w2      = (const float*)d_in[5];
    const float* b2      = (const float*)d_in[6];
    const float* omega2  = (const float*)d_in[7];
    const float* w3      = (const float*)d_in[8];
    const float* b3      = (const float*)d_in[9];
    const float* bias    = (const float*)d_in[10];
    float* out = (float*)d_out;

    transpose_kernel<<<dim3(64, 32), dim3(32, 8)>>>(x);
    gen_kernel<<<dim3(16, 8), 256>>>(rel_pos, w1, b1, omega1, w2, b2, omega2, w3, b3);
    conv_kernel<<<dim3(16, 32), 256>>>(bias, out);
}

// round 3
// speedup vs baseline: 22.3889x; 22.3604x over previous
#include <cuda_runtime.h>

#define BB    32
#define CINC  32
#define COUTC 32
#define TT    2048
#define DKK   32
#define NFFT  4096

// ---- scratch (device globals; allocation-free) -----------------------------
__device__ float  g_buf[COUTC * CINC * TT];   // [o*32+i][d]  8 MB
__device__ float2 Xf[1024 * NFFT];            // [b*32+i][f] 32 MB
__device__ float2 Gf[1024 * NFFT];            // [o*32+i][f] 32 MB
__device__ float2 Of[1024 * NFFT];            // [b*32+o][f] 32 MB
__device__ float2 twid[1024];                 // exp(-2πi t/4096), t<1024

__device__ __forceinline__ float2 cmulf(float2 a, float2 b) {
    return make_float2(a.x * b.x - a.y * b.y, a.x * b.y + a.y * b.x);
}
__device__ __forceinline__ float2 caddf(float2 a, float2 b) { return make_float2(a.x + b.x, a.y + b.y); }
__device__ __forceinline__ float2 csubf(float2 a, float2 b) { return make_float2(a.x - b.x, a.y - b.y); }

// ---------------------------------------------------------------------------
__global__ void twiddle_kernel() {
    int t = blockIdx.x * 256 + threadIdx.x;
    double ang = -2.0 * 3.14159265358979323846 * (double)t / (double)NFFT;
    twid[t] = make_float2((float)cos(ang), (float)sin(ang));
}

// ---------------------------------------------------------------------------
// SIREN MLP -> g_buf.  g[o,i,d] = kern[o,i,2048-d], d in [0,2048).
// grid (16, 8), 256 threads.  (verified in R1)
// ---------------------------------------------------------------------------
__global__ void gen_kernel(const float* __restrict__ rel_pos,
                           const float* __restrict__ w1,
                           const float* __restrict__ b1,
                           const float* __restrict__ omega1p,
                           const float* __restrict__ w2,
                           const float* __restrict__ b2,
                           const float* __restrict__ omega2p,
                           const float* __restrict__ w3,
                           const float* __restrict__ b3) {
    __shared__ float h2s[128][33];
    const int tid = threadIdx.x;

    if (tid < 128) {
        const int kl = tid;
        const int k  = 1 + blockIdx.x * 128 + kl;   // k in [1, 2048]
        const float pos = rel_pos[k];
        const float o1 = *omega1p, o2 = *omega2p;
        float h1[DKK];
#pragma unroll
        for (int j = 0; j < DKK; j++)
            h1[j] = sinf(o1 * (w1[j] * pos + b1[j]));
        for (int j = 0; j < DKK; j++) {
            float a = b2[j];
#pragma unroll
            for (int l = 0; l < DKK; l++)
                a += w2[j * DKK + l] * h1[l];
            h2s[kl][j] = sinf(o2 * a);
        }
    }
    __syncthreads();

    const int kl   = tid & 127;
    const int half = tid >> 7;
    const int k    = 1 + blockIdx.x * 128 + kl;
    const int d    = 2048 - k;                       // d in [0, 2047]
    const int j2b  = blockIdx.y * 128 + half * 64;
    for (int jj = 0; jj < 64; jj++) {
        const int j2 = j2b + jj;
        float a = b3[j2];
#pragma unroll
        for (int l = 0; l < DKK; l++)
            a += w3[j2 * DKK + l] * h2s[kl][l];
        g_buf[j2 * TT + d] = a;
    }
}

// ---------------------------------------------------------------------------
// 4096-pt radix-4 Stockham FFT (natural order in/out), one signal per block.
// 256 threads, 4 butterflies each per stage; single smem buffer with
// read-all -> sync -> write-all per stage.
// MODE 0: real x (from rsrc)   -> Xf[sig]
// MODE 1: real g (from g_buf)  -> Gf[sig]
// MODE 2: complex Of[sig]      -> inverse FFT -> rdst (real*1/N + bias[o])
// ---------------------------------------------------------------------------
template<int MODE>
__global__ void __launch_bounds__(256)
fft4096_kernel(const float* __restrict__ rsrc,
               float* __restrict__ rdst,
               const float* __restrict__ bias) {
    constexpr bool INV = (MODE == 2);
    __shared__ float2 buf[NFFT];     // 32 KB
    __shared__ float2 tws[1024];     //  8 KB
    const int tid = threadIdx.x;
    const int sig = blockIdx.x;

#pragma unroll
    for (int k = 0; k < 4; k++) tws[tid + 256 * k] = twid[tid + 256 * k];

    if (MODE == 0 || MODE == 1) {
        const float* base = (MODE == 0) ? (rsrc + (size_t)sig * TT)
                                        : (g_buf + (size_t)sig * TT);
        const float4* src = (const float4*)base;
#pragma unroll
        for (int k = 0; k < 2; k++) {
            float4 v = src[tid + 256 * k];
            int b = 4 * (tid + 256 * k);
            buf[b + 0] = make_float2(v.x, 0.f);
            buf[b + 1] = make_float2(v.y, 0.f);
            buf[b + 2] = make_float2(v.z, 0.f);
            buf[b + 3] = make_float2(v.w, 0.f);
        }
#pragma unroll
        for (int k = 0; k < 8; k++)
            buf[2048 + tid + 256 * k] = make_float2(0.f, 0.f);
    } else {
        const float2* src = Of + (size_t)sig * NFFT;
#pragma unroll
        for (int k = 0; k < 16; k++) buf[tid + 256 * k] = src[tid + 256 * k];
    }
    __syncthreads();

    int m = 1;
#pragma unroll
    for (int s = 0; s < 6; s++, m <<= 2) {
        float2 av[4], bv[4], cv[4], dv[4];
#pragma unroll
        for (int v = 0; v < 4; v++) {
            int u = tid + 256 * v;           // reads: u + 1024*r, every stage
            av[v] = buf[u];
            bv[v] = buf[u + 1024];
            cv[v] = buf[u + 2048];
            dv[v] = buf[u + 3072];
        }
        __syncthreads();
#pragma unroll
        for (int v = 0; v < 4; v++) {
            int u  = tid + 256 * v;
            int k  = u & (m - 1);
            int jm = u - k;                  // j*m, < 1024
            float2 W1 = tws[jm];
            if (INV) W1.y = -W1.y;
            float2 W2 = cmulf(W1, W1);
            float2 W3 = cmulf(W2, W1);
            float2 t0 = caddf(av[v], cv[v]);
            float2 t1 = csubf(av[v], cv[v]);
            float2 t2 = caddf(bv[v], dv[v]);
            float2 t3 = csubf(bv[v], dv[v]);
            // fwd: -i*(b-d) = ( y, -x);  inv: +i*(b-d) = (-y, x)
            float2 t3r = INV ? make_float2(-t3.y, t3.x)
                             : make_float2(t3.y, -t3.x);
            int wb = 4 * jm + k;
            buf[wb]         = caddf(t0, t2);
            buf[wb + m]     = cmulf(caddf(t1, t3r), W1);
            buf[wb + 2 * m] = cmulf(csubf(t0, t2), W2);
            buf[wb + 3 * m] = cmulf(csubf(t1, t3r), W3);
        }
        __syncthreads();
    }

    if (MODE == 0) {
        float2* dst = Xf + (size_t)sig * NFFT;
#pragma unroll
        for (int k = 0; k < 16; k++) dst[tid + 256 * k] = buf[tid + 256 * k];
    } else if (MODE == 1) {
        float2* dst = Gf + (size_t)sig * NFFT;
#pragma unroll
        for (int k = 0; k < 16; k++) dst[tid + 256 * k] = buf[tid + 256 * k];
    } else {
        const float sc  = 1.0f / (float)NFFT;
        const float bvv = bias[sig & 31];    // sig = b*32 + o
        float* dst = rdst + (size_t)sig * TT;
#pragma unroll
        for (int k = 0; k < 8; k++)
            dst[tid + 256 * k] = buf[tid + 256 * k].x * sc + bvv;
    }
}

// ---------------------------------------------------------------------------
// Pointwise per-frequency complex GEMM:
//   Of[b,o,f] = sum_i Xf[b,i,f] * Gf[o,i,f]
// grid (512, 4, 4) = (f-chunk of 8, b-tile of 8, o-tile of 8), 256 threads.
// smem layout [i][row][ff] -> warp compute reads are contiguous (no conflicts).
// ---------------------------------------------------------------------------
__global__ void __launch_bounds__(256)
pointwise_kernel() {
    __shared__ float2 Xs[32 * 64];   // [i][bb][ff] 16 KB
    __shared__ float2 Gs[32 * 64];   // [i][oo][ff] 16 KB
    const int tid = threadIdx.x;
    const int f0 = blockIdx.x * 8;
    const int b0 = blockIdx.y * 8;
    const int o0 = blockIdx.z * 8;

#pragma unroll
    for (int q = 0; q < 4; q++) {
        int flat4 = tid + 256 * q;          // float4 index == i*32 + rr*4 + ffp
        int ffp = flat4 & 3;
        int rr  = (flat4 >> 2) & 7;
        int i   = flat4 >> 5;
        const float4* xsrc = (const float4*)(Xf + ((size_t)((b0 + rr) * 32 + i)) * NFFT + f0);
        const float4* gsrc = (const float4*)(Gf + ((size_t)((o0 + rr) * 32 + i)) * NFFT + f0);
        ((float4*)Xs)[flat4] = xsrc[ffp];
        ((float4*)Gs)[flat4] = gsrc[ffp];
    }
    __syncthreads();

    const int ff = tid & 7;
    const int oo = (tid >> 3) & 7;
    const int bq = tid >> 6;                 // 0..3 ; handles bb=bq and bb=bq+4
    float2 acc0 = make_float2(0.f, 0.f);
    float2 acc1 = make_float2(0.f, 0.f);
#pragma unroll
    for (int i = 0; i < 32; i++) {
        float2 g  = Gs[i * 64 + oo * 8 + ff];
        float2 xa = Xs[i * 64 + bq * 8 + ff];
        float2 xb = Xs[i * 64 + (bq + 4) * 8 + ff];
        acc0.x += xa.x * g.x - xa.y * g.y;
        acc0.y += xa.x * g.y + xa.y * g.x;
        acc1.x += xb.x * g.x - xb.y * g.y;
        acc1.y += xb.x * g.y + xb.y * g.x;
    }
    Of[((size_t)((b0 + bq)     * 32 + (o0 + oo))) * NFFT + f0 + ff] = acc0;
    Of[((size_t)((b0 + bq + 4) * 32 + (o0 + oo))) * NFFT + f0 + ff] = acc1;
}

// ---------------------------------------------------------------------------
extern "C" void kernel_launch(void* const* d_in, const int* in_sizes, int n_in,
                              void* d_out, int out_size) {
    const float* x       = (const float*)d_in[0];
    const float* rel_pos = (const float*)d_in[1];
    const float* w1      = (const float*)d_in[2];
    const float* b1      = (const float*)d_in[3];
    const float* omega1  = (const float*)d_in[4];
    const float* w2      = (const float*)d_in[5];
    const float* b2      = (const float*)d_in[6];
    const float* omega2  = (const float*)d_in[7];
    const float* w3      = (const float*)d_in[8];
    const float* b3      = (const float*)d_in[9];
    const float* bias    = (const float*)d_in[10];
    float* out = (float*)d_out;

    twiddle_kernel<<<4, 256>>>();
    gen_kernel<<<dim3(16, 8), 256>>>(rel_pos, w1, b1, omega1, w2, b2, omega2, w3, b3);
    fft4096_kernel<0><<<1024, 256>>>(x, nullptr, nullptr);        // x  -> Xf
    fft4096_kernel<1><<<1024, 256>>>(nullptr, nullptr, nullptr);  // g  -> Gf
    pointwise_kernel<<<dim3(512, 4, 4), 256>>>();                 // Xf*Gf -> Of
    fft4096_kernel<2><<<1024, 256>>>(nullptr, out, bias);         // Of -> out
}

// round 4
// speedup vs baseline: 33.5771x; 1.4997x over previous
#include <cuda_runtime.h>

#define BB    32
#define CINC  32
#define COUTC 32
#define TT    2048
#define DKK   32
#define NFFT  4096
#define FH    2056   // half-spectrum row stride (f = 0..2048 valid, 16B-aligned)

// ---- scratch (device globals; allocation-free) -----------------------------
__device__ float  g_buf[COUTC * CINC * TT];   // [o*32+i][d]   8 MB
__device__ float2 Xf[1024 * FH];              // [b*32+i][f]  16.8 MB
__device__ float2 Gf[1024 * FH];              // [o*32+i][f]  16.8 MB
__device__ float2 Of[1024 * FH];              // [b*32+o][f]  16.8 MB
__device__ float2 twid[1024];                 // exp(-2πi t/4096), t<1024

__device__ __forceinline__ float2 cmulf(float2 a, float2 b) {
    return make_float2(a.x * b.x - a.y * b.y, a.x * b.y + a.y * b.x);
}
__device__ __forceinline__ float2 caddf(float2 a, float2 b) { return make_float2(a.x + b.x, a.y + b.y); }
__device__ __forceinline__ float2 csubf(float2 a, float2 b) { return make_float2(a.x - b.x, a.y - b.y); }

// ---------------------------------------------------------------------------
__global__ void twiddle_kernel() {
    int t = blockIdx.x * 256 + threadIdx.x;
    double ang = -2.0 * 3.14159265358979323846 * (double)t / (double)NFFT;
    twid[t] = make_float2((float)cos(ang), (float)sin(ang));
}

// ---------------------------------------------------------------------------
// SIREN MLP -> g_buf.  g[o,i,d] = kern[o,i,2048-d], d in [0,2048). (verified R1)
// ---------------------------------------------------------------------------
__global__ void gen_kernel(const float* __restrict__ rel_pos,
                           const float* __restrict__ w1,
                           const float* __restrict__ b1,
                           const float* __restrict__ omega1p,
                           const float* __restrict__ w2,
                           const float* __restrict__ b2,
                           const float* __restrict__ omega2p,
                           const float* __restrict__ w3,
                           const float* __restrict__ b3) {
    __shared__ float h2s[128][33];
    const int tid = threadIdx.x;

    if (tid < 128) {
        const int kl = tid;
        const int k  = 1 + blockIdx.x * 128 + kl;   // k in [1, 2048]
        const float pos = rel_pos[k];
        const float o1 = *omega1p, o2 = *omega2p;
        float h1[DKK];
#pragma unroll
        for (int j = 0; j < DKK; j++)
            h1[j] = sinf(o1 * (w1[j] * pos + b1[j]));
        for (int j = 0; j < DKK; j++) {
            float a = b2[j];
#pragma unroll
            for (int l = 0; l < DKK; l++)
                a += w2[j * DKK + l] * h1[l];
            h2s[kl][j] = sinf(o2 * a);
        }
    }
    __syncthreads();

    const int kl   = tid & 127;
    const int half = tid >> 7;
    const int k    = 1 + blockIdx.x * 128 + kl;
    const int d    = 2048 - k;
    const int j2b  = blockIdx.y * 128 + half * 64;
    for (int jj = 0; jj < 64; jj++) {
        const int j2 = j2b + jj;
        float a = b3[j2];
#pragma unroll
        for (int l = 0; l < DKK; l++)
            a += w3[j2 * DKK + l] * h2s[kl][l];
        g_buf[j2 * TT + d] = a;
    }
}

// ---------------------------------------------------------------------------
// 4096-pt radix-4 Stockham FFT, packed-real, one block per *pair* of signals.
// MODE 0: z = x_row(2ip) + i*x_row(2ip+1)  -> unpack -> Xf half-spectra
// MODE 1: same from g_buf                  -> Gf half-spectra
// MODE 2: rebuild full spectrum of O1 + i*O2 from Of half-spectra,
//         inverse FFT, write two real rows (scaled 1/N, + bias)
// sig = blockIdx.x in [0,512): hb = sig>>4 (b or o-pair-group), ip = sig&15.
// ---------------------------------------------------------------------------
template<int MODE>
__global__ void __launch_bounds__(256)
fft4096_kernel(const float* __restrict__ rsrc,
               float* __restrict__ rdst,
               const float* __restrict__ bias) {
    constexpr bool INV = (MODE == 2);
    __shared__ float2 buf[NFFT];     // 32 KB
    __shared__ float2 tws[1024];     //  8 KB
    const int tid = threadIdx.x;
    const int sig = blockIdx.x;
    const int hb  = sig >> 4;        // b (MODE 0,2) or o-group (MODE 1)
    const int ip  = sig & 15;
    const int rowA = hb * 32 + 2 * ip;

#pragma unroll
    for (int k = 0; k < 4; k++) tws[tid + 256 * k] = twid[tid + 256 * k];

    if (MODE == 0 || MODE == 1) {
        const float* baseA = (MODE == 0) ? (rsrc + (size_t)rowA * TT)
                                         : (g_buf + (size_t)rowA * TT);
        const float4* srcA = (const float4*)baseA;
        const float4* srcB = (const float4*)(baseA + TT);
#pragma unroll
        for (int k = 0; k < 2; k++) {
            int idx = tid + 256 * k;
            float4 va = srcA[idx];
            float4 vb = srcB[idx];
            int t0 = 4 * idx;
            buf[t0 + 0] = make_float2(va.x, vb.x);
            buf[t0 + 1] = make_float2(va.y, vb.y);
            buf[t0 + 2] = make_float2(va.z, vb.z);
            buf[t0 + 3] = make_float2(va.w, vb.w);
        }
#pragma unroll
        for (int k = 0; k < 8; k++)
            buf[2048 + tid + 256 * k] = make_float2(0.f, 0.f);
    } else {
        const float2* srcA = Of + (size_t)rowA * FH;
        const float2* srcB = srcA + FH;
#pragma unroll
        for (int k = 0; k < 8; k++) {
            int f = tid + 256 * k;               // 0..2047
            float2 o1 = srcA[f];
            float2 o2 = srcB[f];
            buf[f] = make_float2(o1.x - o2.y, o1.y + o2.x);
            if (f > 0)
                buf[NFFT - f] = make_float2(o1.x + o2.y, o2.x - o1.y);
        }
        if (tid == 0) {
            float2 o1 = srcA[2048];
            float2 o2 = srcB[2048];
            buf[2048] = make_float2(o1.x - o2.y, o1.y + o2.x);
        }
    }
    __syncthreads();

    int m = 1;
#pragma unroll
    for (int s = 0; s < 6; s++, m <<= 2) {
        float2 av[4], bv[4], cv[4], dv[4];
#pragma unroll
        for (int v = 0; v < 4; v++) {
            int u = tid + 256 * v;
            av[v] = buf[u];
            bv[v] = buf[u + 1024];
            cv[v] = buf[u + 2048];
            dv[v] = buf[u + 3072];
        }
        __syncthreads();
#pragma unroll
        for (int v = 0; v < 4; v++) {
            int u  = tid + 256 * v;
            int k  = u & (m - 1);
            int jm = u - k;
            float2 W1 = tws[jm];
            if (INV) W1.y = -W1.y;
            float2 W2 = cmulf(W1, W1);
            float2 W3 = cmulf(W2, W1);
            float2 t0 = caddf(av[v], cv[v]);
            float2 t1 = csubf(av[v], cv[v]);
            float2 t2 = caddf(bv[v], dv[v]);
            float2 t3 = csubf(bv[v], dv[v]);
            float2 t3r = INV ? make_float2(-t3.y, t3.x)
                             : make_float2(t3.y, -t3.x);
            int wb = 4 * jm + k;
            buf[wb]         = caddf(t0, t2);
            buf[wb + m]     = cmulf(caddf(t1, t3r), W1);
            buf[wb + 2 * m] = cmulf(csubf(t0, t2), W2);
            buf[wb + 3 * m] = cmulf(csubf(t1, t3r), W3);
        }
        __syncthreads();
    }

    if (MODE == 0 || MODE == 1) {
        // Unpack: A[f] = 0.5(Z[f]+conj(Z[N-f])), B[f] = -0.5i(Z[f]-conj(Z[N-f]))
        float2* dstA = ((MODE == 0) ? Xf : Gf) + (size_t)rowA * FH;
        float2* dstB = dstA + FH;
#pragma unroll
        for (int k = 0; k < 8; k++) {
            int f  = tid + 256 * k;              // 0..2047
            int fm = (NFFT - f) & (NFFT - 1);
            float2 z  = buf[f];
            float2 zm = buf[fm];
            dstA[f] = make_float2(0.5f * (z.x + zm.x), 0.5f * (z.y - zm.y));
            dstB[f] = make_float2(0.5f * (z.y + zm.y), 0.5f * (zm.x - z.x));
        }
        if (tid == 0) {
            float2 z = buf[2048];
            dstA[2048] = make_float2(z.x, 0.f);
            dstB[2048] = make_float2(z.y, 0.f);
        }
    } else {
        const float sc = 1.0f / (float)NFFT;
        const float bv1 = bias[(rowA) & 31];
        const float bv2 = bias[(rowA + 1) & 31];
        float* dst1 = rdst + (size_t)rowA * TT;
        float* dst2 = dst1 + TT;
#pragma unroll
        for (int k = 0; k < 8; k++) {
            int t = tid + 256 * k;
            float2 z = buf[t];
            dst1[t] = z.x * sc + bv1;
            dst2[t] = z.y * sc + bv2;
        }
    }
}

// ---------------------------------------------------------------------------
// Pointwise per-frequency complex GEMM on the half-spectrum:
//   Of[b,o,f] = sum_i Xf[b,i,f] * Gf[o,i,f],  f in [0, 2056) (valid <= 2048)
// grid (257, 2, 2) = (f-chunk 8, b-tile 16, o-tile 16), 256 threads.
// i processed in chunks of 8 via 16 KB smem; 8 float2 accumulators/thread.
// ---------------------------------------------------------------------------
__global__ void __launch_bounds__(256)
pointwise_kernel() {
    __shared__ float2 Xs[8 * 16 * 8];   // [ii][bb][ff] 8 KB
    __shared__ float2 Gs[8 * 16 * 8];   // [ii][oo][ff] 8 KB
    const int tid = threadIdx.x;
    const int f0 = blockIdx.x * 8;
    const int b0 = blockIdx.y * 16;
    const int o0 = blockIdx.z * 16;
    const int ff = tid & 7;
    const int oo = (tid >> 3) & 15;
    const int bh = tid >> 7;            // 0..1

    float2 acc[8];
#pragma unroll
    for (int j = 0; j < 8; j++) acc[j] = make_float2(0.f, 0.f);

    for (int ic = 0; ic < 32; ic += 8) {
        __syncthreads();
#pragma unroll
        for (int q = 0; q < 2; q++) {
            int flat4 = tid + 256 * q;          // = ii*64 + rr*4 + ffp
            int ffp = flat4 & 3;
            int rr  = (flat4 >> 2) & 15;
            int ii  = flat4 >> 6;
            const float4* xsrc = (const float4*)(Xf + ((size_t)((b0 + rr) * 32 + ic + ii)) * FH + f0);
            const float4* gsrc = (const float4*)(Gf + ((size_t)((o0 + rr) * 32 + ic + ii)) * FH + f0);
            ((float4*)Xs)[flat4] = xsrc[ffp];
            ((float4*)Gs)[flat4] = gsrc[ffp];
        }
        __syncthreads();
#pragma unroll
        for (int ii = 0; ii < 8; ii++) {
            float2 g = Gs[(ii * 16 + oo) * 8 + ff];
#pragma unroll
            for (int bb = 0; bb < 8; bb++) {
                float2 xv = Xs[(ii * 16 + bh * 8 + bb) * 8 + ff];
                acc[bb].x += xv.x * g.x - xv.y * g.y;
                acc[bb].y += xv.x * g.y + xv.y * g.x;
            }
        }
    }
#pragma unroll
    for (int bb = 0; bb < 8; bb++)
        Of[((size_t)((b0 + bh * 8 + bb) * 32 + o0 + oo)) * FH + f0 + ff] = acc[bb];
}

// ---------------------------------------------------------------------------
extern "C" void kernel_launch(void* const* d_in, const int* in_sizes, int n_in,
                              void* d_out, int out_size) {
    const float* x       = (const float*)d_in[0];
    const float* rel_pos = (const float*)d_in[1];
    const float* w1      = (const float*)d_in[2];
    const float* b1      = (const float*)d_in[3];
    const float* omega1  = (const float*)d_in[4];
    const float* w2      = (const float*)d_in[5];
    const float* b2      = (const float*)d_in[6];
    const float* omega2  = (const float*)d_in[7];
    const float* w3      = (const float*)d_in[8];
    const float* b3      = (const float*)d_in[9];
    const float* bias    = (const float*)d_in[10];
    float* out = (float*)d_out;

    twiddle_kernel<<<4, 256>>>();
    gen_kernel<<<dim3(16, 8), 256>>>(rel_pos, w1, b1, omega1, w2, b2, omega2, w3, b3);
    fft4096_kernel<0><<<512, 256>>>(x, nullptr, nullptr);         // x pairs -> Xf
    fft4096_kernel<1><<<512, 256>>>(nullptr, nullptr, nullptr);   // g pairs -> Gf
    pointwise_kernel<<<dim3(257, 2, 2), 256>>>();                 // Xf*Gf -> Of (half)
    fft4096_kernel<2><<<512, 256>>>(nullptr, out, bias);          // Of -> out (pairs)
}

// round 6
// speedup vs baseline: 35.6313x; 1.0612x over previous
#include <cuda_runtime.h>

#define BB    32
#define CINC  32
#define COUTC 32
#define TT    2048
#define DKK   32
#define NFFT  4096
#define FH    2064   // half-spectrum row stride (f = 0..2048 valid; 16-float2 aligned)

// FFT dynamic smem: 2 signal buffers + shared twiddle table
#define FFT_SMEM_BYTES ((2 * NFFT + 1024) * sizeof(float2))   // 73728

// ---- scratch (device globals; allocation-free) -----------------------------
__device__ float  g_buf[COUTC * CINC * TT];   // [o*32+i][d]   8 MB
__device__ float2 Xf[1024 * FH];              // [b*32+i][f]  16.9 MB
__device__ float2 Gf[1024 * FH];              // [o*32+i][f]  16.9 MB
__device__ float2 Of[1024 * FH];              // [b*32+o][f]  16.9 MB
__device__ float2 twid[1024];                 // exp(-2πi t/4096), t<1024

__device__ __forceinline__ float2 cmulf(float2 a, float2 b) {
    return make_float2(a.x * b.x - a.y * b.y, a.x * b.y + a.y * b.x);
}
__device__ __forceinline__ float2 caddf(float2 a, float2 b) { return make_float2(a.x + b.x, a.y + b.y); }
__device__ __forceinline__ float2 csubf(float2 a, float2 b) { return make_float2(a.x - b.x, a.y - b.y); }

// ---------------------------------------------------------------------------
__global__ void twiddle_kernel() {
    int t = blockIdx.x * 256 + threadIdx.x;
    double ang = -2.0 * 3.14159265358979323846 * (double)t / (double)NFFT;
    twid[t] = make_float2((float)cos(ang), (float)sin(ang));
}

// ---------------------------------------------------------------------------
// SIREN MLP -> g_buf.  g[o,i,d] = kern[o,i,2048-d], d in [0,2048). (verified R1)
// ---------------------------------------------------------------------------
__global__ void gen_kernel(const float* __restrict__ rel_pos,
                           const float* __restrict__ w1,
                           const float* __restrict__ b1,
                           const float* __restrict__ omega1p,
                           const float* __restrict__ w2,
                           const float* __restrict__ b2,
                           const float* __restrict__ omega2p,
                           const float* __restrict__ w3,
                           const float* __restrict__ b3) {
    __shared__ float h2s[128][33];
    const int tid = threadIdx.x;

    if (tid < 128) {
        const int kl = tid;
        const int k  = 1 + blockIdx.x * 128 + kl;   // k in [1, 2048]
        const float pos = rel_pos[k];
        const float o1 = *omega1p, o2 = *omega2p;
        float h1[DKK];
#pragma unroll
        for (int j = 0; j < DKK; j++)
            h1[j] = sinf(o1 * (w1[j] * pos + b1[j]));
        for (int j = 0; j < DKK; j++) {
            float a = b2[j];
#pragma unroll
            for (int l = 0; l < DKK; l++)
                a += w2[j * DKK + l] * h1[l];
            h2s[kl][j] = sinf(o2 * a);
        }
    }
    __syncthreads();

    const int kl   = tid & 127;
    const int half = tid >> 7;
    const int k    = 1 + blockIdx.x * 128 + kl;
    const int d    = 2048 - k;
    const int j2b  = blockIdx.y * 128 + half * 64;
    for (int jj = 0; jj < 64; jj++) {
        const int j2 = j2b + jj;
        float a = b3[j2];
#pragma unroll
        for (int l = 0; l < DKK; l++)
            a += w3[j2 * DKK + l] * h2s[kl][l];
        g_buf[j2 * TT + d] = a;
    }
}

// ---------------------------------------------------------------------------
// 4096-pt radix-4 Stockham FFT, packed-real, TWO signal-pairs per block
// (512 threads = 2 x 256; sub = tid>>8 selects the pair, tid2 = tid&255).
// Dynamic smem: [2*NFFT buf | 1024 twiddles].
// MODE 0: z = x_row(2ip) + i*x_row(2ip+1)  -> unpack -> Xf half-spectra
// MODE 1: same from g_buf                  -> Gf half-spectra
// MODE 2: rebuild full spectrum of O1 + i*O2 from Of half-spectra,
//         inverse FFT, write two real rows (scaled 1/N, + bias)
// ---------------------------------------------------------------------------
template<int MODE>
__global__ void __launch_bounds__(512)
fft4096_kernel(const float* __restrict__ rsrc,
               float* __restrict__ rdst,
               const float* __restrict__ bias) {
    constexpr bool INV = (MODE == 2);
    extern __shared__ float2 dyn[];
    float2* bufs = dyn;                 // 2 * NFFT
    float2* tws  = dyn + 2 * NFFT;      // 1024
    const int tid  = threadIdx.x;
    const int sub  = tid >> 8;
    const int tid2 = tid & 255;
    float2* buf = bufs + sub * NFFT;

    const int sig = blockIdx.x * 2 + sub;     // pair index in [0,512)
    const int hb  = sig >> 4;                 // b (MODE 0,2) or o-group (MODE 1)
    const int ip  = sig & 15;
    const int rowA = hb * 32 + 2 * ip;

#pragma unroll
    for (int k = 0; k < 2; k++) tws[tid + 512 * k] = twid[tid + 512 * k];

    if (MODE == 0 || MODE == 1) {
        const float* baseA = (MODE == 0) ? (rsrc + (size_t)rowA * TT)
                                         : (g_buf + (size_t)rowA * TT);
        const float4* srcA = (const float4*)baseA;
        const float4* srcB = (const float4*)(baseA + TT);
#pragma unroll
        for (int k = 0; k < 2; k++) {
            int idx = tid2 + 256 * k;
            float4 va = srcA[idx];
            float4 vb = srcB[idx];
            int t0 = 4 * idx;
            buf[t0 + 0] = make_float2(va.x, vb.x);
            buf[t0 + 1] = make_float2(va.y, vb.y);
            buf[t0 + 2] = make_float2(va.z, vb.z);
            buf[t0 + 3] = make_float2(va.w, vb.w);
        }
#pragma unroll
        for (int k = 0; k < 8; k++)
            buf[2048 + tid2 + 256 * k] = make_float2(0.f, 0.f);
    } else {
        const float2* srcA = Of + (size_t)rowA * FH;
        const float2* srcB = srcA + FH;
#pragma unroll
        for (int k = 0; k < 8; k++) {
            int f = tid2 + 256 * k;               // 0..2047
            float2 o1 = srcA[f];
            float2 o2 = srcB[f];
            buf[f] = make_float2(o1.x - o2.y, o1.y + o2.x);
            if (f > 0)
                buf[NFFT - f] = make_float2(o1.x + o2.y, o2.x - o1.y);
        }
        if (tid2 == 0) {
            float2 o1 = srcA[2048];
            float2 o2 = srcB[2048];
            buf[2048] = make_float2(o1.x - o2.y, o1.y + o2.x);
        }
    }
    __syncthreads();

    int m = 1;
#pragma unroll
    for (int s = 0; s < 6; s++, m <<= 2) {
        float2 av[4], bv[4], cv[4], dv[4];
#pragma unroll
        for (int v = 0; v < 4; v++) {
            int u = tid2 + 256 * v;
            av[v] = buf[u];
            bv[v] = buf[u + 1024];
            cv[v] = buf[u + 2048];
            dv[v] = buf[u + 3072];
        }
        __syncthreads();
#pragma unroll
        for (int v = 0; v < 4; v++) {
            int u  = tid2 + 256 * v;
            int k  = u & (m - 1);
            int jm = u - k;
            float2 W1 = tws[jm];
            if (INV) W1.y = -W1.y;
            float2 W2 = cmulf(W1, W1);
            float2 W3 = cmulf(W2, W1);
            float2 t0 = caddf(av[v], cv[v]);
            float2 t1 = csubf(av[v], cv[v]);
            float2 t2 = caddf(bv[v], dv[v]);
            float2 t3 = csubf(bv[v], dv[v]);
            float2 t3r = INV ? make_float2(-t3.y, t3.x)
                             : make_float2(t3.y, -t3.x);
            int wb = 4 * jm + k;
            buf[wb]         = caddf(t0, t2);
            buf[wb + m]     = cmulf(caddf(t1, t3r), W1);
            buf[wb + 2 * m] = cmulf(csubf(t0, t2), W2);
            buf[wb + 3 * m] = cmulf(csubf(t1, t3r), W3);
        }
        __syncthreads();
    }

    if (MODE == 0 || MODE == 1) {
        // Unpack: A[f] = 0.5(Z[f]+conj(Z[N-f])), B[f] = -0.5i(Z[f]-conj(Z[N-f]))
        float2* dstA = ((MODE == 0) ? Xf : Gf) + (size_t)rowA * FH;
        float2* dstB = dstA + FH;
#pragma unroll
        for (int k = 0; k < 8; k++) {
            int f  = tid2 + 256 * k;              // 0..2047
            int fm = (NFFT - f) & (NFFT - 1);
            float2 z  = buf[f];
            float2 zm = buf[fm];
            dstA[f] = make_float2(0.5f * (z.x + zm.x), 0.5f * (z.y - zm.y));
            dstB[f] = make_float2(0.5f * (z.y + zm.y), 0.5f * (zm.x - z.x));
        }
        if (tid2 == 0) {
            float2 z = buf[2048];
            dstA[2048] = make_float2(z.x, 0.f);
            dstB[2048] = make_float2(z.y, 0.f);
        }
    } else {
        const float sc = 1.0f / (float)NFFT;
        const float bv1 = bias[(rowA) & 31];
        const float bv2 = bias[(rowA + 1) & 31];
        float* dst1 = rdst + (size_t)rowA * TT;
        float* dst2 = dst1 + TT;
#pragma unroll
        for (int k = 0; k < 8; k++) {
            int t = tid2 + 256 * k;
            float2 z = buf[t];
            dst1[t] = z.x * sc + bv1;
            dst2[t] = z.y * sc + bv2;
        }
    }
}

// ---------------------------------------------------------------------------
// Pointwise per-frequency complex GEMM (one-wave register GEMM):
//   Of[b,o,f] = sum_i Xf[b,i,f] * Gf[o,i,f]
// grid (129), 512 threads; block = all 32 b x 32 o for a 16-wide f tile.
// Thread = (ff, oo-quad, bb-oct): 4x8 complex accumulators in registers.
// i in chunks of 4 staged in 32 KB smem; x reads are half-warp broadcasts.
// ---------------------------------------------------------------------------
__global__ void __launch_bounds__(512)
pointwise_kernel() {
    __shared__ float2 Xs[4 * 32 * 16];   // [ii][b][ff] 16 KB
    __shared__ float2 Gs[4 * 32 * 16];   // [ii][o][ff] 16 KB
    const int tid = threadIdx.x;
    const int f0  = blockIdx.x * 16;
    const int ff  = tid & 15;
    const int oo0 = ((tid >> 4) & 7) * 4;
    const int bb0 = (tid >> 7) * 8;

    float2 acc[4][8];
#pragma unroll
    for (int j = 0; j < 4; j++)
#pragma unroll
        for (int l = 0; l < 8; l++) acc[j][l] = make_float2(0.f, 0.f);

    for (int ic = 0; ic < 32; ic += 4) {
        __syncthreads();
#pragma unroll
        for (int q = 0; q < 2; q++) {
            int flat4 = tid + 512 * q;        // = ii*256 + rr*8 + f4
            int f4 = flat4 & 7;
            int rr = (flat4 >> 3) & 31;
            int ii = flat4 >> 8;
            int row = rr * 32 + ic + ii;      // b*32+i  (== o*32+i)
            ((float4*)Xs)[flat4] = ((const float4*)(Xf + (size_t)row * FH + f0))[f4];
            ((float4*)Gs)[flat4] = ((const float4*)(Gf + (size_t)row * FH + f0))[f4];
        }
        __syncthreads();
#pragma unroll
        for (int ii = 0; ii < 4; ii++) {
            float2 xv[8], gv[4];
#pragma unroll
            for (int l = 0; l < 8; l++)
                xv[l] = Xs[(ii * 32 + bb0 + l) * 16 + ff];
#pragma unroll
            for (int j = 0; j < 4; j++)
                gv[j] = Gs[(ii * 32 + oo0 + j) * 16 + ff];
#pragma unroll
            for (int j = 0; j < 4; j++)
#pragma unroll
                for (int l = 0; l < 8; l++) {
                    acc[j][l].x += xv[l].x * gv[j].x - xv[l].y * gv[j].y;
                    acc[j][l].y += xv[l].x * gv[j].y + xv[l].y * gv[j].x;
                }
        }
    }
#pragma unroll
    for (int j = 0; j < 4; j++)
#pragma unroll
        for (int l = 0; l < 8; l++)
            Of[(size_t)((bb0 + l) * 32 + oo0 + j) * FH + f0 + ff] = acc[j][l];
}

// ---------------------------------------------------------------------------
extern "C" void kernel_launch(void* const* d_in, const int* in_sizes, int n_in,
                              void* d_out, int out_size) {
    const float* x       = (const float*)d_in[0];
    const float* rel_pos = (const float*)d_in[1];
    const float* w1      = (const float*)d_in[2];
    const float* b1      = (const float*)d_in[3];
    const float* omega1  = (const float*)d_in[4];
    const float* w2      = (const float*)d_in[5];
    const float* b2      = (const float*)d_in[6];
    const float* omega2  = (const float*)d_in[7];
    const float* w3      = (const float*)d_in[8];
    const float* b3      = (const float*)d_in[9];
    const float* bias    = (const float*)d_in[10];
    float* out = (float*)d_out;

    // Raise dynamic-smem ceiling for the FFT kernels (host attr set; idempotent,
    // no allocation, graph-capture-safe).
    cudaFuncSetAttribute(fft4096_kernel<0>, cudaFuncAttributeMaxDynamicSharedMemorySize, FFT_SMEM_BYTES);
    cudaFuncSetAttribute(fft4096_kernel<1>, cudaFuncAttributeMaxDynamicSharedMemorySize, FFT_SMEM_BYTES);
    cudaFuncSetAttribute(fft4096_kernel<2>, cudaFuncAttributeMaxDynamicSharedMemorySize, FFT_SMEM_BYTES);

    twiddle_kernel<<<4, 256>>>();
    gen_kernel<<<dim3(16, 8), 256>>>(rel_pos, w1, b1, omega1, w2, b2, omega2, w3, b3);
    fft4096_kernel<0><<<256, 512, FFT_SMEM_BYTES>>>(x, nullptr, nullptr);        // x pairs -> Xf
    fft4096_kernel<1><<<256, 512, FFT_SMEM_BYTES>>>(nullptr, nullptr, nullptr);  // g pairs -> Gf
    pointwise_kernel<<<129, 512>>>();                                            // Xf*Gf -> Of
    fft4096_kernel<2><<<256, 512, FFT_SMEM_BYTES>>>(nullptr, out, bias);         // Of -> out
}

// round 7
// speedup vs baseline: 60.1212x; 1.6873x over previous
#include <cuda_runtime.h>

#define BB    32
#define CINC  32
#define COUTC 32
#define TT    2048
#define DKK   32
#define NFFT  4096
#define FH    2064   // half-spectrum row stride (f = 0..2048 valid; 16-float2 aligned)

// FFT dynamic smem: 4096-pt buffer + 512-entry twiddle table
#define FFT_SMEM_BYTES ((NFFT + 512) * sizeof(float2))   // 36864

// smem bank-conflict swizzle for the FFT buffer (float2 index domain)
#define SW(i) ((i) ^ ((((i) >> 5) & 7) << 1))

// ---- scratch (device globals; allocation-free) -----------------------------
__device__ float  g_buf[COUTC * CINC * TT];   // [o*32+i][d]   8 MB
__device__ float2 Xf[1024 * FH];              // [b*32+i][f]
__device__ float2 Gf[1024 * FH];              // [o*32+i][f]
__device__ float2 Of[1024 * FH];              // [b*32+o][f]
__device__ float2 twid[512];                  // exp(-2πi t/4096), t<512

__device__ __forceinline__ float2 cmulf(float2 a, float2 b) {
    return make_float2(a.x * b.x - a.y * b.y, a.x * b.y + a.y * b.x);
}
__device__ __forceinline__ float2 caddf(float2 a, float2 b) { return make_float2(a.x + b.x, a.y + b.y); }
__device__ __forceinline__ float2 csubf(float2 a, float2 b) { return make_float2(a.x - b.x, a.y - b.y); }

// packed f32x2 helpers (Blackwell FFMA2)
typedef unsigned long long ull;
__device__ __forceinline__ ull pk2(float lo, float hi) {
    ull d; asm("mov.b64 %0, {%1, %2};" : "=l"(d) : "f"(lo), "f"(hi)); return d;
}
__device__ __forceinline__ void upk2(float& lo, float& hi, ull v) {
    asm("mov.b64 {%0, %1}, %2;" : "=f"(lo), "=f"(hi) : "l"(v));
}
__device__ __forceinline__ ull fma2(ull a, ull b, ull c) {
    ull d; asm("fma.rn.f32x2 %0, %1, %2, %3;" : "=l"(d) : "l"(a), "l"(b), "l"(c)); return d;
}

// ---------------------------------------------------------------------------
__global__ void twiddle_kernel() {
    int t = blockIdx.x * 256 + threadIdx.x;
    double ang = -2.0 * 3.14159265358979323846 * (double)t / (double)NFFT;
    twid[t] = make_float2((float)cos(ang), (float)sin(ang));
}

// ---------------------------------------------------------------------------
// SIREN MLP -> g_buf.  g[o,i,d] = kern[o,i,2048-d], d in [0,2048).
// grid (16, 8), 256 threads. w3 tile staged in smem; h2 row in registers.
// ---------------------------------------------------------------------------
__global__ void __launch_bounds__(256)
gen_kernel(const float* __restrict__ rel_pos,
           const float* __restrict__ w1,
           const float* __restrict__ b1,
           const float* __restrict__ omega1p,
           const float* __restrict__ w2,
           const float* __restrict__ b2,
           const float* __restrict__ omega2p,
           const float* __restrict__ w3,
           const float* __restrict__ b3) {
    __shared__ float h2s[128][33];
    __shared__ float w3s[128][32];
    __shared__ float b3s[128];
    const int tid = threadIdx.x;
    const int j2b0 = blockIdx.y * 128;

    // load w3 tile [j2b0 .. j2b0+128) x 32  (coalesced float4)
#pragma unroll
    for (int q = 0; q < 4; q++) {
        int flat4 = tid + 256 * q;          // float4 index: row*8 + c4
        int row = flat4 >> 3;
        int c4  = flat4 & 7;
        ((float4*)&w3s[row][0])[c4] = ((const float4*)(w3 + (size_t)(j2b0 + row) * 32))[c4];
    }
    if (tid < 128) b3s[tid] = b3[j2b0 + tid];

    if (tid < 128) {
        const int kl = tid;
        const int k  = 1 + blockIdx.x * 128 + kl;   // k in [1, 2048]
        const float pos = rel_pos[k];
        const float o1 = *omega1p, o2 = *omega2p;
        float h1[DKK];
#pragma unroll
        for (int j = 0; j < DKK; j++)
            h1[j] = sinf(o1 * (w1[j] * pos + b1[j]));
        for (int j = 0; j < DKK; j++) {
            float a = b2[j];
#pragma unroll
            for (int l = 0; l < DKK; l++)
                a += w2[j * DKK + l] * h1[l];
            h2s[kl][j] = sinf(o2 * a);
        }
    }
    __syncthreads();

    const int kl   = tid & 127;
    const int half = tid >> 7;
    const int k    = 1 + blockIdx.x * 128 + kl;
    const int d    = 2048 - k;
    // hoist this thread's h2 row into registers (conflict-free: stride 33)
    float h2r[32];
#pragma unroll
    for (int l = 0; l < 32; l++) h2r[l] = h2s[kl][l];

    for (int jj = 0; jj < 64; jj++) {
        const int row = half * 64 + jj;
        float a = b3s[row];
#pragma unroll
        for (int l4 = 0; l4 < 8; l4++) {
            float4 w = ((const float4*)&w3s[row][0])[l4];   // LDS.128 broadcast
            a += w.x * h2r[4*l4+0] + w.y * h2r[4*l4+1]
               + w.z * h2r[4*l4+2] + w.w * h2r[4*l4+3];
        }
        g_buf[(size_t)(j2b0 + row) * TT + d] = a;
    }
}

// ---------------------------------------------------------------------------
// 4096-pt radix-8 Stockham FFT (4 stages), packed-real, ONE pair per block.
// 512 threads: one radix-8 butterfly per thread per stage. Swizzled smem.
// MODE 0: z = x_row(2ip) + i*x_row(2ip+1)  -> unpack -> Xf half-spectra
// MODE 1: same from g_buf                  -> Gf half-spectra
// MODE 2: rebuild full spectrum of O1 + i*O2 from Of half-spectra,
//         inverse FFT, write two real rows (scaled 1/N, + bias)
// ---------------------------------------------------------------------------
template<int MODE>
__global__ void __launch_bounds__(512, 2)
fft4096_kernel(const float* __restrict__ rsrc,
               float* __restrict__ rdst,
               const float* __restrict__ bias) {
    constexpr bool INV = (MODE == 2);
    extern __shared__ float2 dyn[];
    float2* buf = dyn;                 // NFFT (swizzled indexing)
    float2* tws = dyn + NFFT;          // 512
    const int tid = threadIdx.x;

    const int sig = blockIdx.x;               // pair index in [0,512)
    const int hb  = sig >> 4;                 // b (MODE 0,2) or o-group (MODE 1)
    const int ip  = sig & 15;
    const int rowA = hb * 32 + 2 * ip;

    tws[tid & 511] = twid[tid & 511];

    if (MODE == 0 || MODE == 1) {
        const float* baseA = (MODE == 0) ? (rsrc + (size_t)rowA * TT)
                                         : (g_buf + (size_t)rowA * TT);
        float4 va = ((const float4*)baseA)[tid];
        float4 vb = ((const float4*)(baseA + TT))[tid];
        int t0 = 4 * tid;
        buf[SW(t0 + 0)] = make_float2(va.x, vb.x);
        buf[SW(t0 + 1)] = make_float2(va.y, vb.y);
        buf[SW(t0 + 2)] = make_float2(va.z, vb.z);
        buf[SW(t0 + 3)] = make_float2(va.w, vb.w);
#pragma unroll
        for (int q = 0; q < 4; q++)
            buf[SW(2048 + tid + 512 * q)] = make_float2(0.f, 0.f);
    } else {
        const float2* srcA = Of + (size_t)rowA * FH;
        const float2* srcB = srcA + FH;
#pragma unroll
        for (int q = 0; q < 4; q++) {
            int f = tid + 512 * q;               // 0..2047
            float2 o1 = srcA[f];
            float2 o2 = srcB[f];
            buf[SW(f)] = make_float2(o1.x - o2.y, o1.y + o2.x);
            if (f > 0)
                buf[SW(NFFT - f)] = make_float2(o1.x + o2.y, o2.x - o1.y);
        }
        if (tid == 0) {
            float2 o1 = srcA[2048];
            float2 o2 = srcB[2048];
            buf[SW(2048)] = make_float2(o1.x - o2.y, o1.y + o2.x);
        }
    }
    __syncthreads();

    const float C = 0.70710678118654752440f;
    int m = 1;
#pragma unroll
    for (int s = 0; s < 4; s++, m <<= 3) {
        const int u  = tid;
        const int k  = u & (m - 1);
        const int jm = u - k;                  // j*m, < 512

        float2 a0 = buf[SW(u)];
        float2 a1 = buf[SW(u +  512)];
        float2 a2 = buf[SW(u + 1024)];
        float2 a3 = buf[SW(u + 1536)];
        float2 a4 = buf[SW(u + 2048)];
        float2 a5 = buf[SW(u + 2560)];
        float2 a6 = buf[SW(u + 3072)];
        float2 a7 = buf[SW(u + 3584)];
        __syncthreads();

        float2 t0 = caddf(a0, a4), t1 = csubf(a0, a4);
        float2 t2 = caddf(a2, a6), t3 = csubf(a2, a6);
        float2 t4 = caddf(a1, a5), t5 = csubf(a1, a5);
        float2 t6 = caddf(a3, a7), t7 = csubf(a3, a7);
        float2 t3r = INV ? make_float2(-t3.y, t3.x) : make_float2(t3.y, -t3.x);
        float2 t7r = INV ? make_float2(-t7.y, t7.x) : make_float2(t7.y, -t7.x);

        float2 e0 = caddf(t0, t2), e2 = csubf(t0, t2);
        float2 e1 = caddf(t1, t3r), e3 = csubf(t1, t3r);
        float2 o0 = caddf(t4, t6), o2 = csubf(t4, t6);
        float2 o1 = caddf(t5, t7r), o3 = csubf(t5, t7r);

        // w8^r rotations on odd outputs
        float2 o1r = INV ? make_float2(C * (o1.x - o1.y), C * (o1.x + o1.y))
                         : make_float2(C * (o1.x + o1.y), C * (o1.y - o1.x));
        float2 o2r = INV ? make_float2(-o2.y, o2.x) : make_float2(o2.y, -o2.x);
        float2 o3r = INV ? make_float2(-C * (o3.x + o3.y), C * (o3.x - o3.y))
                         : make_float2(C * (o3.y - o3.x), -C * (o3.x + o3.y));

        float2 W1 = tws[jm];
        if (INV) W1.y = -W1.y;
        const int wb = 8 * jm + k;

        buf[SW(wb)]         = caddf(e0, o0);
        float2 Wc = W1;
        buf[SW(wb + m)]     = cmulf(caddf(e1, o1r), Wc);
        Wc = cmulf(Wc, W1);
        buf[SW(wb + 2*m)]   = cmulf(caddf(e2, o2r), Wc);
        Wc = cmulf(Wc, W1);
        buf[SW(wb + 3*m)]   = cmulf(caddf(e3, o3r), Wc);
        Wc = cmulf(Wc, W1);
        buf[SW(wb + 4*m)]   = cmulf(csubf(e0, o0), Wc);
        Wc = cmulf(Wc, W1);
        buf[SW(wb + 5*m)]   = cmulf(csubf(e1, o1r), Wc);
        Wc = cmulf(Wc, W1);
        buf[SW(wb + 6*m)]   = cmulf(csubf(e2, o2r), Wc);
        Wc = cmulf(Wc, W1);
        buf[SW(wb + 7*m)]   = cmulf(csubf(e3, o3r), Wc);
        __syncthreads();
    }

    if (MODE == 0 || MODE == 1) {
        // Unpack: A[f] = 0.5(Z[f]+conj(Z[N-f])), B[f] = -0.5i(Z[f]-conj(Z[N-f]))
        float2* dstA = ((MODE == 0) ? Xf : Gf) + (size_t)rowA * FH;
        float2* dstB = dstA + FH;
#pragma unroll
        for (int q = 0; q < 4; q++) {
            int f  = tid + 512 * q;              // 0..2047
            int fm = (NFFT - f) & (NFFT - 1);
            float2 z  = buf[SW(f)];
            float2 zm = buf[SW(fm)];
            dstA[f] = make_float2(0.5f * (z.x + zm.x), 0.5f * (z.y - zm.y));
            dstB[f] = make_float2(0.5f * (z.y + zm.y), 0.5f * (zm.x - z.x));
        }
        if (tid == 0) {
            float2 z = buf[SW(2048)];
            dstA[2048] = make_float2(z.x, 0.f);
            dstB[2048] = make_float2(z.y, 0.f);
        }
    } else {
        const float sc = 1.0f / (float)NFFT;
        const float bv1 = bias[(rowA) & 31];
        const float bv2 = bias[(rowA + 1) & 31];
        float* dst1 = rdst + (size_t)rowA * TT;
        float* dst2 = dst1 + TT;
#pragma unroll
        for (int q = 0; q < 4; q++) {
            int t = tid + 512 * q;
            float2 z = buf[SW(t)];
            dst1[t] = z.x * sc + bv1;
            dst2[t] = z.y * sc + bv2;
        }
    }
}

// ---------------------------------------------------------------------------
// Pointwise per-frequency complex GEMM (one-wave register GEMM, FFMA2):
//   Of[b,o,f] = sum_i Xf[b,i,f] * Gf[o,i,f]
// grid (129), 512 threads; block = all 32 b x 32 o for a 16-wide f tile.
// ---------------------------------------------------------------------------
__global__ void __launch_bounds__(512)
pointwise_kernel() {
    __shared__ float2 Xs[4 * 32 * 16];   // [ii][b][ff] 16 KB
    __shared__ float2 Gs[4 * 32 * 16];   // [ii][o][ff] 16 KB
    const int tid = threadIdx.x;
    const int f0  = blockIdx.x * 16;
    const int ff  = tid & 15;
    const int oo0 = ((tid >> 4) & 7) * 4;
    const int bb0 = (tid >> 7) * 8;

    ull acc[4][8];
#pragma unroll
    for (int j = 0; j < 4; j++)
#pragma unroll
        for (int l = 0; l < 8; l++) acc[j][l] = 0ull;

    for (int ic = 0; ic < 32; ic += 4) {
        __syncthreads();
#pragma unroll
        for (int q = 0; q < 2; q++) {
            int flat4 = tid + 512 * q;        // = ii*256 + rr*8 + f4
            int f4 = flat4 & 7;
            int rr = (flat4 >> 3) & 31;
            int ii = flat4 >> 8;
            int row = rr * 32 + ic + ii;      // b*32+i  (== o*32+i)
            ((float4*)Xs)[flat4] = ((const float4*)(Xf + (size_t)row * FH + f0))[f4];
            ((float4*)Gs)[flat4] = ((const float4*)(Gf + (size_t)row * FH + f0))[f4];
        }
        __syncthreads();
#pragma unroll
        for (int ii = 0; ii < 4; ii++) {
            ull bx[8], by[8], gp[4], gq[4];
#pragma unroll
            for (int l = 0; l < 8; l++) {
                float2 xv = Xs[(ii * 32 + bb0 + l) * 16 + ff];
                bx[l] = pk2(xv.x, xv.x);
                by[l] = pk2(xv.y, xv.y);
            }
#pragma unroll
            for (int j = 0; j < 4; j++) {
                float2 g = Gs[(ii * 32 + oo0 + j) * 16 + ff];
                gp[j] = pk2(g.x, g.y);
                gq[j] = pk2(-g.y, g.x);
            }
#pragma unroll
            for (int j = 0; j < 4; j++)
#pragma unroll
                for (int l = 0; l < 8; l++) {
                    acc[j][l] = fma2(bx[l], gp[j], acc[j][l]);
                    acc[j][l] = fma2(by[l], gq[j], acc[j][l]);
                }
        }
    }
#pragma unroll
    for (int j = 0; j < 4; j++)
#pragma unroll
        for (int l = 0; l < 8; l++) {
            float2 v;
            upk2(v.x, v.y, acc[j][l]);
            Of[(size_t)((bb0 + l) * 32 + oo0 + j) * FH + f0 + ff] = v;
        }
}

// ---------------------------------------------------------------------------
extern "C" void kernel_launch(void* const* d_in, const int* in_sizes, int n_in,
                              void* d_out, int out_size) {
    const float* x       = (const float*)d_in[0];
    const float* rel_pos = (const float*)d_in[1];
    const float* w1      = (const float*)d_in[2];
    const float* b1      = (const float*)d_in[3];
    const float* omega1  = (const float*)d_in[4];
    const float* w2      = (const float*)d_in[5];
    const float* b2      = (const float*)d_in[6];
    const float* omega2  = (const float*)d_in[7];
    const float* w3      = (const float*)d_in[8];
    const float* b3      = (const float*)d_in[9];
    const float* bias    = (const float*)d_in[10];
    float* out = (float*)d_out;

    twiddle_kernel<<<2, 256>>>();
    gen_kernel<<<dim3(16, 8), 256>>>(rel_pos, w1, b1, omega1, w2, b2, omega2, w3, b3);
    fft4096_kernel<0><<<512, 512, FFT_SMEM_BYTES>>>(x, nullptr, nullptr);        // x pairs -> Xf
    fft4096_kernel<1><<<512, 512, FFT_SMEM_BYTES>>>(nullptr, nullptr, nullptr);  // g pairs -> Gf
    pointwise_kernel<<<129, 512>>>();                                            // Xf*Gf -> Of
    fft4096_kernel<2><<<512, 512, FFT_SMEM_BYTES>>>(nullptr, out, bias);         // Of -> out
}

// round 8
// speedup vs baseline: 75.3837x; 1.2539x over previous
#include <cuda_runtime.h>

#define BB    32
#define CINC  32
#define COUTC 32
#define TT    2048
#define DKK   32
#define NFFT  4096
#define FH    2064   // half-spectrum row stride (f = 0..2048 valid; 16-float2 aligned)

// FFT dynamic smem: 4096-pt buffer + 256-entry twiddle table
#define FFT_SMEM_BYTES ((NFFT + 256) * sizeof(float2))   // 34816

// smem bank-conflict swizzle for the FFT buffer (float2 index domain)
#define SW(i) ((i) ^ ((((i) >> 4) & 15)))

// ---- scratch (device globals; allocation-free) -----------------------------
__device__ float  g_buf[COUTC * CINC * TT];   // [o*32+i][d]   8 MB
__device__ float2 Xf[1024 * FH];              // [b*32+i][f]
__device__ float2 Gf[1024 * FH];              // [o*32+i][f]
__device__ float2 Of[1024 * FH];              // [b*32+o][f]

__device__ __forceinline__ float2 cmulf(float2 a, float2 b) {
    return make_float2(a.x * b.x - a.y * b.y, a.x * b.y + a.y * b.x);
}
__device__ __forceinline__ float2 caddf(float2 a, float2 b) { return make_float2(a.x + b.x, a.y + b.y); }
__device__ __forceinline__ float2 csubf(float2 a, float2 b) { return make_float2(a.x - b.x, a.y - b.y); }

// packed f32x2 helpers (Blackwell FFMA2)
typedef unsigned long long ull;
__device__ __forceinline__ ull pk2(float lo, float hi) {
    ull d; asm("mov.b64 %0, {%1, %2};" : "=l"(d) : "f"(lo), "f"(hi)); return d;
}
__device__ __forceinline__ void upk2(float& lo, float& hi, ull v) {
    asm("mov.b64 {%0, %1}, %2;" : "=f"(lo), "=f"(hi) : "l"(v));
}
__device__ __forceinline__ ull fma2(ull a, ull b, ull c) {
    ull d; asm("fma.rn.f32x2 %0, %1, %2, %3;" : "=l"(d) : "l"(a), "l"(b), "l"(c)); return d;
}

// ---------------------------------------------------------------------------
// 16-point DFT codelet (registers only). a[n] in, A[r] out (in place).
// A[4r1+r0] = DFT4_{n0}( w16^{±n0*r0} * DFT4_{n1}( a[4n1+n0] )[r0] )[r1]
// ---------------------------------------------------------------------------
template<bool INV>
__device__ __forceinline__ void dft16(float2* a) {
    const float c1 = 0.92387953251128675613f;
    const float s1 = 0.38268343236508977173f;
    const float Cc = 0.70710678118654752440f;
    float2 B[16];
#pragma unroll
    for (int n0 = 0; n0 < 4; n0++) {
        float2 p0 = a[n0], p1 = a[4 + n0], p2 = a[8 + n0], p3 = a[12 + n0];
        float2 t0 = caddf(p0, p2), t1 = csubf(p0, p2);
        float2 t2 = caddf(p1, p3), t3 = csubf(p1, p3);
        float2 t3r = INV ? make_float2(-t3.y, t3.x) : make_float2(t3.y, -t3.x);
        B[n0 * 4 + 0] = caddf(t0, t2);
        B[n0 * 4 + 1] = caddf(t1, t3r);
        B[n0 * 4 + 2] = csubf(t0, t2);
        B[n0 * 4 + 3] = csubf(t1, t3r);
    }
    // pre-twiddles w16^{n0*r0} (conjugated for inverse)
    const float sg = INV ? 1.f : -1.f;
    const float2 w1 = make_float2(c1, sg * s1);
    const float2 w2 = make_float2(Cc, sg * Cc);
    const float2 w3 = make_float2(s1, sg * c1);
    const float2 w6 = make_float2(-Cc, sg * Cc);
    const float2 w9 = make_float2(-c1, -sg * s1);
    B[5]  = cmulf(B[5],  w1);
    B[6]  = cmulf(B[6],  w2);
    B[7]  = cmulf(B[7],  w3);
    B[9]  = cmulf(B[9],  w2);
    B[10] = INV ? make_float2(-B[10].y, B[10].x) : make_float2(B[10].y, -B[10].x); // w16^4
    B[11] = cmulf(B[11], w6);
    B[13] = cmulf(B[13], w3);
    B[14] = cmulf(B[14], w6);
    B[15] = cmulf(B[15], w9);
#pragma unroll
    for (int r0 = 0; r0 < 4; r0++) {
        float2 p0 = B[r0], p1 = B[4 + r0], p2 = B[8 + r0], p3 = B[12 + r0];
        float2 t0 = caddf(p0, p2), t1 = csubf(p0, p2);
        float2 t2 = caddf(p1, p3), t3 = csubf(p1, p3);
        float2 t3r = INV ? make_float2(-t3.y, t3.x) : make_float2(t3.y, -t3.x);
        a[r0]      = caddf(t0, t2);
        a[4 + r0]  = caddf(t1, t3r);
        a[8 + r0]  = csubf(t0, t2);
        a[12 + r0] = csubf(t1, t3r);
    }
}

// ---------------------------------------------------------------------------
// SIREN MLP -> g_buf.  g[o,i,d] = kern[o,i,2048-d], d in [0,2048).
// ---------------------------------------------------------------------------
__global__ void __launch_bounds__(256)
gen_kernel(const float* __restrict__ rel_pos,
           const float* __restrict__ w1,
           const float* __restrict__ b1,
           const float* __restrict__ omega1p,
           const float* __restrict__ w2,
           const float* __restrict__ b2,
           const float* __restrict__ omega2p,
           const float* __restrict__ w3,
           const float* __restrict__ b3) {
    __shared__ float h2s[128][33];
    __shared__ float w3s[128][32];
    __shared__ float b3s[128];
    const int tid = threadIdx.x;
    const int j2b0 = blockIdx.y * 128;

#pragma unroll
    for (int q = 0; q < 4; q++) {
        int flat4 = tid + 256 * q;
        int row = flat4 >> 3;
        int c4  = flat4 & 7;
        ((float4*)&w3s[row][0])[c4] = ((const float4*)(w3 + (size_t)(j2b0 + row) * 32))[c4];
    }
    if (tid < 128) b3s[tid] = b3[j2b0 + tid];

    if (tid < 128) {
        const int kl = tid;
        const int k  = 1 + blockIdx.x * 128 + kl;
        const float pos = rel_pos[k];
        const float o1 = *omega1p, o2 = *omega2p;
        float h1[DKK];
#pragma unroll
        for (int j = 0; j < DKK; j++)
            h1[j] = sinf(o1 * (w1[j] * pos + b1[j]));
        for (int j = 0; j < DKK; j++) {
            float a = b2[j];
#pragma unroll
            for (int l = 0; l < DKK; l++)
                a += w2[j * DKK + l] * h1[l];
            h2s[kl][j] = sinf(o2 * a);
        }
    }
    __syncthreads();

    const int kl   = tid & 127;
    const int half = tid >> 7;
    const int k    = 1 + blockIdx.x * 128 + kl;
    const int d    = 2048 - k;
    float h2r[32];
#pragma unroll
    for (int l = 0; l < 32; l++) h2r[l] = h2s[kl][l];

    for (int jj = 0; jj < 64; jj++) {
        const int row = half * 64 + jj;
        float a = b3s[row];
#pragma unroll
        for (int l4 = 0; l4 < 8; l4++) {
            float4 w = ((const float4*)&w3s[row][0])[l4];
            a += w.x * h2r[4*l4+0] + w.y * h2r[4*l4+1]
               + w.z * h2r[4*l4+2] + w.w * h2r[4*l4+3];
        }
        g_buf[(size_t)(j2b0 + row) * TT + d] = a;
    }
}

// ---------------------------------------------------------------------------
// 4096-pt radix-16 Stockham FFT (3 stages), packed-real, one pair per block.
// 256 threads, 16 elements each. Twiddles computed in-kernel (sincospif).
// FWD (INV=false): blockIdx.x<512 -> x rows -> Xf ; >=512 -> g rows -> Gf
// INV: rebuild full spectrum of O1 + i*O2 from Of, inverse, write out+bias.
// ---------------------------------------------------------------------------
template<bool INV>
__global__ void __launch_bounds__(256, 3)
fft4096_kernel(const float* __restrict__ rsrc,
               float* __restrict__ rdst,
               const float* __restrict__ bias) {
    extern __shared__ float2 dyn[];
    float2* buf = dyn;                 // NFFT (swizzled indexing)
    float2* tws = dyn + NFFT;          // 256
    const int tid = threadIdx.x;

    const int sig = INV ? blockIdx.x : (blockIdx.x & 511);   // pair index
    const int isG = INV ? 0 : (blockIdx.x >> 9);
    const int hb  = sig >> 4;
    const int ip  = sig & 15;
    const int rowA = hb * 32 + 2 * ip;

    {   // twiddle table: exp(-2*pi*i*t/4096), t < 256
        float s, c;
        sincospif(-(float)tid / 2048.0f, &s, &c);
        tws[tid] = make_float2(c, s);
    }

    if (!INV) {
        const float* baseA = isG ? (g_buf + (size_t)rowA * TT)
                                 : (rsrc + (size_t)rowA * TT);
#pragma unroll
        for (int q = 0; q < 2; q++) {
            int idx = tid + 256 * q;
            float4 va = ((const float4*)baseA)[idx];
            float4 vb = ((const float4*)(baseA + TT))[idx];
            int t0 = 4 * idx;
            buf[SW(t0 + 0)] = make_float2(va.x, vb.x);
            buf[SW(t0 + 1)] = make_float2(va.y, vb.y);
            buf[SW(t0 + 2)] = make_float2(va.z, vb.z);
            buf[SW(t0 + 3)] = make_float2(va.w, vb.w);
        }
#pragma unroll
        for (int q = 0; q < 8; q++)
            buf[SW(2048 + tid + 256 * q)] = make_float2(0.f, 0.f);
    } else {
        const float2* srcA = Of + (size_t)rowA * FH;
        const float2* srcB = srcA + FH;
#pragma unroll
        for (int q = 0; q < 8; q++) {
            int f = tid + 256 * q;               // 0..2047
            float2 o1 = srcA[f];
            float2 o2 = srcB[f];
            buf[SW(f)] = make_float2(o1.x - o2.y, o1.y + o2.x);
            if (f > 0)
                buf[SW(NFFT - f)] = make_float2(o1.x + o2.y, o2.x - o1.y);
        }
        if (tid == 0) {
            float2 o1 = srcA[2048];
            float2 o2 = srcB[2048];
            buf[SW(2048)] = make_float2(o1.x - o2.y, o1.y + o2.x);
        }
    }
    __syncthreads();

    int m = 1;
#pragma unroll
    for (int s = 0; s < 3; s++, m <<= 4) {
        float2 a[16];
#pragma unroll
        for (int r = 0; r < 16; r++)
            a[r] = buf[SW(tid + 256 * r)];
        __syncthreads();

        dft16<INV>(a);

        const int k  = tid & (m - 1);
        const int jm = tid - k;                  // < 256
        const int wb = 16 * jm + k;
        if (s < 2) {
            float2 W1 = tws[jm];
            if (INV) W1.y = -W1.y;
            buf[SW(wb)] = a[0];
            float2 Wc = W1;
#pragma unroll
            for (int r = 1; r < 16; r++) {
                buf[SW(wb + r * m)] = cmulf(a[r], Wc);
                Wc = cmulf(Wc, W1);
            }
        } else {
            // last stage: jm == 0, twiddles are all 1
#pragma unroll
            for (int r = 0; r < 16; r++)
                buf[SW(wb + r * m)] = a[r];
        }
        __syncthreads();
    }

    if (!INV) {
        // Unpack: A[f] = 0.5(Z[f]+conj(Z[N-f])), B[f] = -0.5i(Z[f]-conj(Z[N-f]))
        float2* dstA = (isG ? Gf : Xf) + (size_t)rowA * FH;
        float2* dstB = dstA + FH;
#pragma unroll
        for (int q = 0; q < 8; q++) {
            int f  = tid + 256 * q;              // 0..2047
            int fm = (NFFT - f) & (NFFT - 1);
            float2 z  = buf[SW(f)];
            float2 zm = buf[SW(fm)];
            dstA[f] = make_float2(0.5f * (z.x + zm.x), 0.5f * (z.y - zm.y));
            dstB[f] = make_float2(0.5f * (z.y + zm.y), 0.5f * (zm.x - z.x));
        }
        if (tid == 0) {
            float2 z = buf[SW(2048)];
            dstA[2048] = make_float2(z.x, 0.f);
            dstB[2048] = make_float2(z.y, 0.f);
        }
    } else {
        const float sc = 1.0f / (float)NFFT;
        const float bv1 = bias[(rowA) & 31];
        const float bv2 = bias[(rowA + 1) & 31];
        float* dst1 = rdst + (size_t)rowA * TT;
        float* dst2 = dst1 + TT;
#pragma unroll
        for (int q = 0; q < 8; q++) {
            int t = tid + 256 * q;
            float2 z = buf[SW(t)];
            dst1[t] = z.x * sc + bv1;
            dst2[t] = z.y * sc + bv2;
        }
    }
}

// ---------------------------------------------------------------------------
// Pointwise per-frequency complex GEMM (one-wave register GEMM, FFMA2):
//   Of[b,o,f] = sum_i Xf[b,i,f] * Gf[o,i,f]
// grid (129), 512 threads; block = all 32 b x 32 o for a 16-wide f tile.
// ---------------------------------------------------------------------------
__global__ void __launch_bounds__(512)
pointwise_kernel() {
    __shared__ float2 Xs[4 * 32 * 16];   // [ii][b][ff] 16 KB
    __shared__ float2 Gs[4 * 32 * 16];   // [ii][o][ff] 16 KB
    const int tid = threadIdx.x;
    const int f0  = blockIdx.x * 16;
    const int ff  = tid & 15;
    const int oo0 = ((tid >> 4) & 7) * 4;
    const int bb0 = (tid >> 7) * 8;

    ull acc[4][8];
#pragma unroll
    for (int j = 0; j < 4; j++)
#pragma unroll
        for (int l = 0; l < 8; l++) acc[j][l] = 0ull;

    for (int ic = 0; ic < 32; ic += 4) {
        __syncthreads();
#pragma unroll
        for (int q = 0; q < 2; q++) {
            int flat4 = tid + 512 * q;        // = ii*256 + rr*8 + f4
            int f4 = flat4 & 7;
            int rr = (flat4 >> 3) & 31;
            int ii = flat4 >> 8;
            int row = rr * 32 + ic + ii;      // b*32+i  (== o*32+i)
            ((float4*)Xs)[flat4] = ((const float4*)(Xf + (size_t)row * FH + f0))[f4];
            ((float4*)Gs)[flat4] = ((const float4*)(Gf + (size_t)row * FH + f0))[f4];
        }
        __syncthreads();
#pragma unroll
        for (int ii = 0; ii < 4; ii++) {
            ull gp[4], gq[4];
#pragma unroll
            for (int j = 0; j < 4; j++) {
                float2 g = Gs[(ii * 32 + oo0 + j) * 16 + ff];
                gp[j] = pk2(g.x, g.y);
                gq[j] = pk2(-g.y, g.x);
            }
#pragma unroll
            for (int l = 0; l < 8; l++) {
                float2 xv = Xs[(ii * 32 + bb0 + l) * 16 + ff];
                ull bx = pk2(xv.x, xv.x);
                ull by = pk2(xv.y, xv.y);
#pragma unroll
                for (int j = 0; j < 4; j++) {
                    acc[j][l] = fma2(bx, gp[j], acc[j][l]);
                    acc[j][l] = fma2(by, gq[j], acc[j][l]);
                }
            }
        }
    }
#pragma unroll
    for (int j = 0; j < 4; j++)
#pragma unroll
        for (int l = 0; l < 8; l++) {
            float2 v;
            upk2(v.x, v.y, acc[j][l]);
            Of[(size_t)((bb0 + l) * 32 + oo0 + j) * FH + f0 + ff] = v;
        }
}

// ---------------------------------------------------------------------------
extern "C" void kernel_launch(void* const* d_in, const int* in_sizes, int n_in,
                              void* d_out, int out_size) {
    const float* x       = (const float*)d_in[0];
    const float* rel_pos = (const float*)d_in[1];
    const float* w1      = (const float*)d_in[2];
    const float* b1      = (const float*)d_in[3];
    const float* omega1  = (const float*)d_in[4];
    const float* w2      = (const float*)d_in[5];
    const float* b2      = (const float*)d_in[6];
    const float* omega2  = (const float*)d_in[7];
    const float* w3      = (const float*)d_in[8];
    const float* b3      = (const float*)d_in[9];
    const float* bias    = (const float*)d_in[10];
    float* out = (float*)d_out;

    gen_kernel<<<dim3(16, 8), 256>>>(rel_pos, w1, b1, omega1, w2, b2, omega2, w3, b3);
    fft4096_kernel<false><<<1024, 256, FFT_SMEM_BYTES>>>(x, nullptr, nullptr);  // x->Xf, g->Gf
    pointwise_kernel<<<129, 512>>>();                                           // Xf*Gf -> Of
    fft4096_kernel<true><<<512, 256, FFT_SMEM_BYTES>>>(nullptr, out, bias);     // Of -> out
}

// round 9
// speedup vs baseline: 77.4867x; 1.0279x over previous
#include <cuda_runtime.h>

#define BB    32
#define CINC  32
#define COUTC 32
#define TT    2048
#define DKK   32
#define NFFT  4096
#define FH    2064   // half-spectrum row stride (f = 0..2048 valid; 16-float2 aligned)

// FFT dynamic smem: 4096-pt buffer + 256-entry twiddle table
#define FFT_SMEM_BYTES ((NFFT + 256) * sizeof(float2))   // 34816

// smem bank-conflict swizzle for the FFT buffer (float2 index domain)
#define SW(i) ((i) ^ ((((i) >> 4) & 15)))

// ---- scratch (device globals; allocation-free) -----------------------------
__device__ float  g_buf[COUTC * CINC * TT];   // [o*32+i][d]   8 MB
__device__ float2 Xf[1024 * FH];              // [b*32+i][f]
__device__ float2 Gf[1024 * FH];              // [o*32+i][f]
__device__ float2 Of[1024 * FH];              // [b*32+o][f]

__device__ __forceinline__ float2 cmulf(float2 a, float2 b) {
    return make_float2(a.x * b.x - a.y * b.y, a.x * b.y + a.y * b.x);
}
__device__ __forceinline__ float2 caddf(float2 a, float2 b) { return make_float2(a.x + b.x, a.y + b.y); }
__device__ __forceinline__ float2 csubf(float2 a, float2 b) { return make_float2(a.x - b.x, a.y - b.y); }

// packed f32x2 helpers (Blackwell FFMA2)
typedef unsigned long long ull;
__device__ __forceinline__ ull pk2(float lo, float hi) {
    ull d; asm("mov.b64 %0, {%1, %2};" : "=l"(d) : "f"(lo), "f"(hi)); return d;
}
__device__ __forceinline__ void upk2(float& lo, float& hi, ull v) {
    asm("mov.b64 {%0, %1}, %2;" : "=f"(lo), "=f"(hi) : "l"(v));
}
__device__ __forceinline__ ull fma2(ull a, ull b, ull c) {
    ull d; asm("fma.rn.f32x2 %0, %1, %2, %3;" : "=l"(d) : "l"(a), "l"(b), "l"(c)); return d;
}

// ---------------------------------------------------------------------------
// 16-point DFT codelet (registers only, in place).
// A[4r1+r0] = DFT4_{n0}( w16^{±n0*r0} * DFT4_{n1}( a[4n1+n0] )[r0] )[r1]
// ---------------------------------------------------------------------------
template<bool INV>
__device__ __forceinline__ void dft16(float2* a) {
    const float c1 = 0.92387953251128675613f;
    const float s1 = 0.38268343236508977173f;
    const float Cc = 0.70710678118654752440f;
    float2 B[16];
#pragma unroll
    for (int n0 = 0; n0 < 4; n0++) {
        float2 p0 = a[n0], p1 = a[4 + n0], p2 = a[8 + n0], p3 = a[12 + n0];
        float2 t0 = caddf(p0, p2), t1 = csubf(p0, p2);
        float2 t2 = caddf(p1, p3), t3 = csubf(p1, p3);
        float2 t3r = INV ? make_float2(-t3.y, t3.x) : make_float2(t3.y, -t3.x);
        B[n0 * 4 + 0] = caddf(t0, t2);
        B[n0 * 4 + 1] = caddf(t1, t3r);
        B[n0 * 4 + 2] = csubf(t0, t2);
        B[n0 * 4 + 3] = csubf(t1, t3r);
    }
    const float sg = INV ? 1.f : -1.f;
    const float2 w1 = make_float2(c1, sg * s1);
    const float2 w2 = make_float2(Cc, sg * Cc);
    const float2 w3 = make_float2(s1, sg * c1);
    const float2 w6 = make_float2(-Cc, sg * Cc);
    const float2 w9 = make_float2(-c1, -sg * s1);
    B[5]  = cmulf(B[5],  w1);
    B[6]  = cmulf(B[6],  w2);
    B[7]  = cmulf(B[7],  w3);
    B[9]  = cmulf(B[9],  w2);
    B[10] = INV ? make_float2(-B[10].y, B[10].x) : make_float2(B[10].y, -B[10].x);
    B[11] = cmulf(B[11], w6);
    B[13] = cmulf(B[13], w3);
    B[14] = cmulf(B[14], w6);
    B[15] = cmulf(B[15], w9);
#pragma unroll
    for (int r0 = 0; r0 < 4; r0++) {
        float2 p0 = B[r0], p1 = B[4 + r0], p2 = B[8 + r0], p3 = B[12 + r0];
        float2 t0 = caddf(p0, p2), t1 = csubf(p0, p2);
        float2 t2 = caddf(p1, p3), t3 = csubf(p1, p3);
        float2 t3r = INV ? make_float2(-t3.y, t3.x) : make_float2(t3.y, -t3.x);
        a[r0]      = caddf(t0, t2);
        a[4 + r0]  = caddf(t1, t3r);
        a[8 + r0]  = csubf(t0, t2);
        a[12 + r0] = csubf(t1, t3r);
    }
}

// ---------------------------------------------------------------------------
// SIREN MLP -> g_buf.  g[o,i,d] = kern[o,i,2048-d], d in [0,2048).
// ---------------------------------------------------------------------------
__global__ void __launch_bounds__(256)
gen_kernel(const float* __restrict__ rel_pos,
           const float* __restrict__ w1,
           const float* __restrict__ b1,
           const float* __restrict__ omega1p,
           const float* __restrict__ w2,
           const float* __restrict__ b2,
           const float* __restrict__ omega2p,
           const float* __restrict__ w3,
           const float* __restrict__ b3) {
    __shared__ float h2s[128][33];
    __shared__ float w3s[128][32];
    __shared__ float b3s[128];
    const int tid = threadIdx.x;
    const int j2b0 = blockIdx.y * 128;

#pragma unroll
    for (int q = 0; q < 4; q++) {
        int flat4 = tid + 256 * q;
        int row = flat4 >> 3;
        int c4  = flat4 & 7;
        ((float4*)&w3s[row][0])[c4] = ((const float4*)(w3 + (size_t)(j2b0 + row) * 32))[c4];
    }
    if (tid < 128) b3s[tid] = b3[j2b0 + tid];

    if (tid < 128) {
        const int kl = tid;
        const int k  = 1 + blockIdx.x * 128 + kl;
        const float pos = rel_pos[k];
        const float o1 = *omega1p, o2 = *omega2p;
        float h1[DKK];
#pragma unroll
        for (int j = 0; j < DKK; j++)
            h1[j] = sinf(o1 * (w1[j] * pos + b1[j]));
        for (int j = 0; j < DKK; j++) {
            float a = b2[j];
#pragma unroll
            for (int l = 0; l < DKK; l++)
                a += w2[j * DKK + l] * h1[l];
            h2s[kl][j] = sinf(o2 * a);
        }
    }
    __syncthreads();

    const int kl   = tid & 127;
    const int half = tid >> 7;
    const int k    = 1 + blockIdx.x * 128 + kl;
    const int d    = 2048 - k;
    float h2r[32];
#pragma unroll
    for (int l = 0; l < 32; l++) h2r[l] = h2s[kl][l];

    for (int jj = 0; jj < 64; jj++) {
        const int row = half * 64 + jj;
        float a = b3s[row];
#pragma unroll
        for (int l4 = 0; l4 < 8; l4++) {
            float4 w = ((const float4*)&w3s[row][0])[l4];
            a += w.x * h2r[4*l4+0] + w.y * h2r[4*l4+1]
               + w.z * h2r[4*l4+2] + w.w * h2r[4*l4+3];
        }
        g_buf[(size_t)(j2b0 + row) * TT + d] = a;
    }
}

// ---------------------------------------------------------------------------
// 4096-pt radix-16 Stockham FFT (3 stages), packed-real, one pair per block.
// 256 threads, 16 elements each. Stage 0 loads DIRECTLY from global into
// registers (zero padding / Hermitian mirror folded in); inverse stage 2
// stores DIRECTLY from registers to global. Only 2 (INV) / 3 (FWD) smem
// round trips remain.
// FWD: blockIdx.x<512 -> x rows -> Xf ; >=512 -> g rows -> Gf
// INV: full spectrum of O1 + i*O2 rebuilt in the register load; out = re/im.
// ---------------------------------------------------------------------------
template<bool INV>
__global__ void __launch_bounds__(256, 4)
fft4096_kernel(const float* __restrict__ rsrc,
               float* __restrict__ rdst,
               const float* __restrict__ bias) {
    extern __shared__ float2 dyn[];
    float2* buf = dyn;                 // NFFT (swizzled indexing)
    float2* tws = dyn + NFFT;          // 256
    const int tid = threadIdx.x;

    const int sig = INV ? blockIdx.x : (blockIdx.x & 511);   // pair index
    const int isG = INV ? 0 : (blockIdx.x >> 9);
    const int hb  = sig >> 4;
    const int ip  = sig & 15;
    const int rowA = hb * 32 + 2 * ip;

    // twiddle table exp(-2πi t/4096); own entry also used as stage-0 twiddle
    float sv, cv;
    sincospif(-(float)tid / 2048.0f, &sv, &cv);
    tws[tid] = make_float2(cv, sv);

    // ---- stage 0: registers straight from global --------------------------
    float2 a[16];
    if (!INV) {
        const float* baseA = isG ? (g_buf + (size_t)rowA * TT)
                                 : (rsrc + (size_t)rowA * TT);
        const float* baseB = baseA + TT;
#pragma unroll
        for (int r = 0; r < 8; r++) {
            int idx = tid + 256 * r;
            a[r] = make_float2(baseA[idx], baseB[idx]);
        }
#pragma unroll
        for (int r = 8; r < 16; r++) a[r] = make_float2(0.f, 0.f);   // folded
    } else {
        const float2* srcA = Of + (size_t)rowA * FH;
        const float2* srcB = srcA + FH;
#pragma unroll
        for (int r = 0; r < 16; r++) {
            int f = tid + 256 * r;
            if (f <= 2048) {
                float2 o1 = srcA[f], o2 = srcB[f];
                a[r] = make_float2(o1.x - o2.y, o1.y + o2.x);
            } else {
                int fp = NFFT - f;               // 1..2047, reversed-coalesced
                float2 o1 = srcA[fp], o2 = srcB[fp];
                a[r] = make_float2(o1.x + o2.y, o2.x - o1.y);
            }
        }
    }
    dft16<INV>(a);
    {   // jm = tid, k = 0, m = 1 -> own twiddle, no table dependency
        float2 W1 = make_float2(cv, INV ? -sv : sv);
        const int wb = 16 * tid;
        buf[SW(wb)] = a[0];
        float2 Wc = W1;
#pragma unroll
        for (int r = 1; r < 16; r++) {
            buf[SW(wb + r)] = cmulf(a[r], Wc);
            Wc = cmulf(Wc, W1);
        }
    }
    __syncthreads();

    // ---- stage 1: smem -> smem (m = 16) ------------------------------------
    {
#pragma unroll
        for (int r = 0; r < 16; r++) a[r] = buf[SW(tid + 256 * r)];
        __syncthreads();
        dft16<INV>(a);
        const int k  = tid & 15;
        const int jm = tid - k;
        const int wb = 16 * jm + k;
        float2 W1 = tws[jm];
        if (INV) W1.y = -W1.y;
        buf[SW(wb)] = a[0];
        float2 Wc = W1;
#pragma unroll
        for (int r = 1; r < 16; r++) {
            buf[SW(wb + 16 * r)] = cmulf(a[r], Wc);
            Wc = cmulf(Wc, W1);
        }
        __syncthreads();
    }

    // ---- stage 2: smem -> registers (m = 256; jm = 0, no twiddles) --------
#pragma unroll
    for (int r = 0; r < 16; r++) a[r] = buf[SW(tid + 256 * r)];
    dft16<INV>(a);
    // output index of a[r] is exactly tid + 256*r

    if (!INV) {
        // need cross-thread mirror for unpack: one smem round
        __syncthreads();
#pragma unroll
        for (int r = 0; r < 16; r++) buf[SW(tid + 256 * r)] = a[r];
        __syncthreads();
        float2* dstA = (isG ? Gf : Xf) + (size_t)rowA * FH;
        float2* dstB = dstA + FH;
#pragma unroll
        for (int q = 0; q < 8; q++) {
            int f  = tid + 256 * q;              // 0..2047
            int fm = (NFFT - f) & (NFFT - 1);
            float2 z  = buf[SW(f)];
            float2 zm = buf[SW(fm)];
            dstA[f] = make_float2(0.5f * (z.x + zm.x), 0.5f * (z.y - zm.y));
            dstB[f] = make_float2(0.5f * (z.y + zm.y), 0.5f * (zm.x - z.x));
        }
        if (tid == 0) {
            float2 z = buf[SW(2048)];
            dstA[2048] = make_float2(z.x, 0.f);
            dstB[2048] = make_float2(z.y, 0.f);
        }
    } else {
        // direct register -> global store
        const float sc = 1.0f / (float)NFFT;
        const float bv1 = bias[(rowA) & 31];
        const float bv2 = bias[(rowA + 1) & 31];
        float* dst1 = rdst + (size_t)rowA * TT;
        float* dst2 = dst1 + TT;
#pragma unroll
        for (int r = 0; r < 8; r++) {
            int t = tid + 256 * r;
            dst1[t] = a[r].x * sc + bv1;
            dst2[t] = a[r].y * sc + bv2;
        }
        // t >= 2048 (r >= 8) are the zero-padding tail: discarded
    }
}

// ---------------------------------------------------------------------------
// Pointwise per-frequency complex GEMM (one-wave register GEMM, FFMA2):
//   Of[b,o,f] = sum_i Xf[b,i,f] * Gf[o,i,f]
// grid (129), 512 threads; block = all 32 b x 32 o for a 16-wide f tile.
// ---------------------------------------------------------------------------
__global__ void __launch_bounds__(512)
pointwise_kernel() {
    __shared__ float2 Xs[4 * 32 * 16];   // [ii][b][ff] 16 KB
    __shared__ float2 Gs[4 * 32 * 16];   // [ii][o][ff] 16 KB
    const int tid = threadIdx.x;
    const int f0  = blockIdx.x * 16;
    const int ff  = tid & 15;
    const int oo0 = ((tid >> 4) & 7) * 4;
    const int bb0 = (tid >> 7) * 8;

    ull acc[4][8];
#pragma unroll
    for (int j = 0; j < 4; j++)
#pragma unroll
        for (int l = 0; l < 8; l++) acc[j][l] = 0ull;

    for (int ic = 0; ic < 32; ic += 4) {
        __syncthreads();
#pragma unroll
        for (int q = 0; q < 2; q++) {
            int flat4 = tid + 512 * q;        // = ii*256 + rr*8 + f4
            int f4 = flat4 & 7;
            int rr = (flat4 >> 3) & 31;
            int ii = flat4 >> 8;
            int row = rr * 32 + ic + ii;      // b*32+i  (== o*32+i)
            ((float4*)Xs)[flat4] = ((const float4*)(Xf + (size_t)row * FH + f0))[f4];
            ((float4*)Gs)[flat4] = ((const float4*)(Gf + (size_t)row * FH + f0))[f4];
        }
        __syncthreads();
#pragma unroll
        for (int ii = 0; ii < 4; ii++) {
            ull gp[4], gq[4];
#pragma unroll
            for (int j = 0; j < 4; j++) {
                float2 g = Gs[(ii * 32 + oo0 + j) * 16 + ff];
                gp[j] = pk2(g.x, g.y);
                gq[j] = pk2(-g.y, g.x);
            }
#pragma unroll
            for (int l = 0; l < 8; l++) {
                float2 xv = Xs[(ii * 32 + bb0 + l) * 16 + ff];
                ull bx = pk2(xv.x, xv.x);
                ull by = pk2(xv.y, xv.y);
#pragma unroll
                for (int j = 0; j < 4; j++) {
                    acc[j][l] = fma2(bx, gp[j], acc[j][l]);
                    acc[j][l] = fma2(by, gq[j], acc[j][l]);
                }
            }
        }
    }
#pragma unroll
    for (int j = 0; j < 4; j++)
#pragma unroll
        for (int l = 0; l < 8; l++) {
            float2 v;
            upk2(v.x, v.y, acc[j][l]);
            Of[(size_t)((bb0 + l) * 32 + oo0 + j) * FH + f0 + ff] = v;
        }
}

// ---------------------------------------------------------------------------
extern "C" void kernel_launch(void* const* d_in, const int* in_sizes, int n_in,
                              void* d_out, int out_size) {
    const float* x       = (const float*)d_in[0];
    const float* rel_pos = (const float*)d_in[1];
    const float* w1      = (const float*)d_in[2];
    const float* b1      = (const float*)d_in[3];
    const float* omega1  = (const float*)d_in[4];
    const float* w2      = (const float*)d_in[5];
    const float* b2      = (const float*)d_in[6];
    const float* omega2  = (const float*)d_in[7];
    const float* w3      = (const float*)d_in[8];
    const float* b3      = (const float*)d_in[9];
    const float* bias    = (const float*)d_in[10];
    float* out = (float*)d_out;

    gen_kernel<<<dim3(16, 8), 256>>>(rel_pos, w1, b1, omega1, w2, b2, omega2, w3, b3);
    fft4096_kernel<false><<<1024, 256, FFT_SMEM_BYTES>>>(x, nullptr, nullptr);  // x->Xf, g->Gf
    pointwise_kernel<<<129, 512>>>();                                           // Xf*Gf -> Of
    fft4096_kernel<true><<<512, 256, FFT_SMEM_BYTES>>>(nullptr, out, bias);     // Of -> out
}